// round 12
// baseline (speedup 1.0000x reference)
#include <cuda_runtime.h>
#include <cuda_fp16.h>
#include <math_constants.h>
#include <cstdint>

#define Bc 4
#define Nn 2048
#define DIMc 1024
#define HEADc 16
#define INTERc 1024
#define HDc 64
#define SCALEc 0.03125f   // INTER^-0.5 = 2^-5 (exact)
#define LOG2E 1.4426950408889634f
#define ONES_H2 0x3C003C00u   // fp16x2 {1.0, 1.0}

// Scratch (device globals). *_h buffers hold fp16.
__device__ __align__(16) __half g_feat_h[(size_t)Bc * Nn * DIMc];
__device__ __align__(16) __half g_wqkvT_h[(size_t)3 * INTERc * DIMc];   // W^T
__device__ __align__(16) __half g_woutT_h[(size_t)DIMc * INTERc];       // W^T
__device__ __align__(16) __half g_qkv_h[(size_t)Bc * Nn * 3 * INTERc];  // Q scaled, K
__device__ __align__(16) __half g_vT_h[(size_t)Bc * HEADc * HDc * Nn];  // [bh][d][tok]
__device__ __align__(16) __half g_att_h[(size_t)Bc * Nn * INTERc];

// ---------------------------------------------------------------------------
// Helpers
// ---------------------------------------------------------------------------
__device__ __forceinline__ uint32_t smem_u32(const void* p) {
    uint32_t a;
    asm("{ .reg .u64 t; cvta.to.shared.u64 t, %1; cvt.u32.u64 %0, t; }"
        : "=r"(a) : "l"(p));
    return a;
}
// pack two f32 -> f16x2 {hi=b, lo=a}, then exp2 both halves in one MUFU
__device__ __forceinline__ uint32_t ex2_h2(float lo, float hi) {
    uint32_t p;
    asm("cvt.rn.f16x2.f32 %0, %1, %2;" : "=r"(p) : "f"(hi), "f"(lo));
    asm("ex2.approx.f16x2 %0, %0;" : "+r"(p));
    return p;
}
__device__ __forceinline__ void cp16(uint32_t dst, const void* src) {
    asm volatile("cp.async.cg.shared.global [%0], [%1], 16;"
                 :: "r"(dst), "l"(src));
}
#define CP_COMMIT() asm volatile("cp.async.commit_group;" ::: "memory")
#define CP_WAIT1()  asm volatile("cp.async.wait_group 1;" ::: "memory")

#define LDMX4(r0, r1, r2, r3, addr) \
    asm volatile("ldmatrix.sync.aligned.m8n8.x4.shared.b16 {%0,%1,%2,%3}, [%4];" \
                 : "=r"(r0), "=r"(r1), "=r"(r2), "=r"(r3) : "r"(addr))

__device__ __forceinline__ void mma_f16(float c[4],
                                        uint32_t a0, uint32_t a1, uint32_t a2, uint32_t a3,
                                        uint32_t b0, uint32_t b1) {
    asm volatile("mma.sync.aligned.m16n8k16.row.col.f32.f16.f16.f32 "
                 "{%0,%1,%2,%3}, {%4,%5,%6,%7}, {%8,%9}, {%0,%1,%2,%3};"
                 : "+f"(c[0]), "+f"(c[1]), "+f"(c[2]), "+f"(c[3])
                 : "r"(a0), "r"(a1), "r"(a2), "r"(a3), "r"(b0), "r"(b1));
}

// ---------------------------------------------------------------------------
// fp16 casts
// ---------------------------------------------------------------------------
__global__ void h_cast(const float4* __restrict__ in, __half2* __restrict__ out,
                       int n4) {
    int i = blockIdx.x * blockDim.x + threadIdx.x;
    if (i < n4) {
        float4 v = in[i];
        out[2 * i]     = __floats2half2_rn(v.x, v.y);
        out[2 * i + 1] = __floats2half2_rn(v.z, v.w);
    }
}

// in: [K][N] f32, out: [N][K] fp16
__global__ void h_cast_T(const float* __restrict__ in, __half* __restrict__ out,
                         int K, int N) {
    __shared__ float t[32][33];
    const int n0 = blockIdx.x << 5, k0 = blockIdx.y << 5;
    const int c = threadIdx.x & 31, r4 = threadIdx.x >> 5;
#pragma unroll
    for (int rr = 0; rr < 32; rr += 8)
        t[r4 + rr][c] = in[(size_t)(k0 + r4 + rr) * N + n0 + c];
    __syncthreads();
#pragma unroll
    for (int rr = 0; rr < 32; rr += 8)
        out[(size_t)(n0 + r4 + rr) * K + k0 + c] = __float2half_rn(t[c][r4 + rr]);
}

// ---------------------------------------------------------------------------
// fp16 mma.sync GEMM: C = A[M,K] @ Bt[Nc,K]^T, f32 accum.
// CTA 128x128, BK=64, 3-stage cp.async, 8 warps (4x2), warp tile 32x64.
// Prefetch for s+2 issued AFTER the first k-step's MMAs (overlaps LSU burst).
// ---------------------------------------------------------------------------
__global__ __launch_bounds__(256, 2)
void gemm_f16(const __half* __restrict__ A, const __half* __restrict__ Bt,
              __half* __restrict__ Ch, float* __restrict__ Cf,
              __half* __restrict__ vT, int M, int Nc, int K, int mode) {
    extern __shared__ char sm[];
    const uint32_t sb = smem_u32(sm);
    const int tid = threadIdx.x;
    const int wid = tid >> 5, lane = tid & 31;
    const int g = lane >> 2, q = lane & 3;
    const int warp_m = wid >> 1;
    const int warp_n = wid & 1;
    const int brow = blockIdx.y << 7;
    const int bcol = blockIdx.x << 7;
    const int NS = K >> 6;

    const int rowA_l = lane & 15;
    const int selA   = lane >> 4;
    const int rowB_l = (lane & 7) + ((lane >> 4) << 3);
    const int selB   = (lane >> 3) & 1;

    auto load_stage = [&](int s) {
        const int k0 = s << 6;
        uint32_t base = sb + (uint32_t)((s % 3) * 32768);
#pragma unroll
        for (int r = 0; r < 4; r++) {
            int ci = tid + 256 * r;
            int m = ci >> 3, kc = ci & 7;
            cp16(base + (uint32_t)(m * 128 + ((kc ^ (m & 7)) << 4)),
                 A + (size_t)(brow + m) * K + k0 + kc * 8);
        }
#pragma unroll
        for (int r = 0; r < 4; r++) {
            int ci = tid + 256 * r;
            int n = ci >> 3, kc = ci & 7;
            cp16(base + 16384u + (uint32_t)(n * 128 + ((kc ^ (n & 7)) << 4)),
                 Bt + (size_t)(bcol + n) * K + k0 + kc * 8);
        }
    };

    float c[2][8][4] = {};

    load_stage(0); CP_COMMIT();
    load_stage(1); CP_COMMIT();

    for (int s = 0; s < NS; s++) {
        CP_WAIT1();
        __syncthreads();

        const uint32_t sA = sb + (uint32_t)((s % 3) * 32768);
        const uint32_t sB = sA + 16384u;

#pragma unroll
        for (int kk = 0; kk < 4; kk++) {
            uint32_t a[2][4];
            const int chA = kk * 2 + selA;
#pragma unroll
            for (int mt = 0; mt < 2; mt++) {
                int row = warp_m * 32 + mt * 16 + rowA_l;
                LDMX4(a[mt][0], a[mt][1], a[mt][2], a[mt][3],
                      sA + (uint32_t)(row * 128 + ((chA ^ (row & 7)) << 4)));
            }
            uint32_t b[8][2];
            const int chB = kk * 2 + selB;
#pragma unroll
            for (int ntp = 0; ntp < 4; ntp++) {
                int row = warp_n * 64 + ntp * 16 + rowB_l;
                LDMX4(b[2 * ntp][0], b[2 * ntp][1], b[2 * ntp + 1][0], b[2 * ntp + 1][1],
                      sB + (uint32_t)(row * 128 + ((chB ^ (row & 7)) << 4)));
            }
#pragma unroll
            for (int mt = 0; mt < 2; mt++)
#pragma unroll
                for (int nt = 0; nt < 8; nt++)
                    mma_f16(c[mt][nt], a[mt][0], a[mt][1], a[mt][2], a[mt][3],
                            b[nt][0], b[nt][1]);
            if (kk == 0) {   // issue prefetch after first k-step's MMAs
                if (s + 2 < NS) load_stage(s + 2);
                CP_COMMIT();
            }
        }
    }

    if (mode && bcol >= 2 * INTERc) {
        // V tile -> vT [bh][d][tok] fp16 scatter
#pragma unroll
        for (int mt = 0; mt < 2; mt++) {
#pragma unroll
            for (int nt = 0; nt < 8; nt++) {
                int row = brow + warp_m * 32 + mt * 16 + g;
                int col = bcol - 2 * INTERc + warp_n * 64 + nt * 8 + q * 2;
                int bI = row >> 11, tok = row & 2047;
                int h = col >> 6, d = col & 63;
                __half* base = vT + (((size_t)(bI * 16 + h) * 64 + d) * Nn) + tok;
                base[0]      = __float2half_rn(c[mt][nt][0]);
                base[Nn]     = __float2half_rn(c[mt][nt][1]);
                base[8]      = __float2half_rn(c[mt][nt][2]);
                base[Nn + 8] = __float2half_rn(c[mt][nt][3]);
            }
        }
    } else if (mode) {
        const float fs = (bcol < INTERc) ? (SCALEc * LOG2E) : 1.0f;
#pragma unroll
        for (int mt = 0; mt < 2; mt++) {
#pragma unroll
            for (int nt = 0; nt < 8; nt++) {
                int row = brow + warp_m * 32 + mt * 16 + g;
                int col = bcol + warp_n * 64 + nt * 8 + q * 2;
                *(__half2*)(Ch + (size_t)row * Nc + col) =
                    __floats2half2_rn(c[mt][nt][0] * fs, c[mt][nt][1] * fs);
                *(__half2*)(Ch + (size_t)(row + 8) * Nc + col) =
                    __floats2half2_rn(c[mt][nt][2] * fs, c[mt][nt][3] * fs);
            }
        }
    } else {
#pragma unroll
        for (int mt = 0; mt < 2; mt++) {
#pragma unroll
            for (int nt = 0; nt < 8; nt++) {
                int row = brow + warp_m * 32 + mt * 16 + g;
                int col = bcol + warp_n * 64 + nt * 8 + q * 2;
                *(float2*)(Cf + (size_t)row * Nc + col) =
                    make_float2(c[mt][nt][0], c[mt][nt][1]);
                *(float2*)(Cf + (size_t)(row + 8) * Nc + col) =
                    make_float2(c[mt][nt][2], c[mt][nt][3]);
            }
        }
    }
}

// ---------------------------------------------------------------------------
// fp16 MMA flash attention. CTA = 64 Q rows x (b,h); warp (r, jh): 16 rows,
// 32-of-64 keys. Fixed-max softmax, exp via ex2.f16x2, row sums via ones-MMA.
// Smem: 3-stage KV (3 x 16KB) + per-warp P 2KB (16KB) = 64KB.
// ---------------------------------------------------------------------------
__global__ __launch_bounds__(256, 2)
void attn_mma(const __half* __restrict__ qkv, const __half* __restrict__ vT,
              __half* __restrict__ att) {
    extern __shared__ char sm[];
    const uint32_t sb = smem_u32(sm);
    const int tid = threadIdx.x;
    const int wid = tid >> 5, lane = tid & 31;
    const int g = lane >> 2, q = lane & 3;
    const int r = wid >> 1, jh = wid & 1;
    const int bh = blockIdx.y;
    const int bI = bh >> 4, h = bh & 15;
    const int i0 = blockIdx.x << 6;
    const int m0 = r << 4;

    const int rowK_l = (lane & 7) + ((lane >> 4) << 3);
    const int selK   = (lane >> 3) & 1;
    const int rowP_l = lane & 15;
    const int selP   = lane >> 4;

    const size_t RS = 3 * INTERc;
    const __half* Qb = qkv + (size_t)(bI * Nn) * RS + h * HDc;
    const __half* Kb = Qb + INTERc;
    const __half* Vb = vT + (size_t)bh * HDc * Nn;

    uint32_t aq[4][4];
    {
        const __half* q0 = Qb + (size_t)(i0 + m0 + g) * RS;
        const __half* q1 = Qb + (size_t)(i0 + m0 + g + 8) * RS;
#pragma unroll
        for (int kb = 0; kb < 4; kb++) {
            aq[kb][0] = *(const uint32_t*)(q0 + kb * 16 + 2 * q);
            aq[kb][1] = *(const uint32_t*)(q1 + kb * 16 + 2 * q);
            aq[kb][2] = *(const uint32_t*)(q0 + kb * 16 + 2 * q + 8);
            aq[kb][3] = *(const uint32_t*)(q1 + kb * 16 + 2 * q + 8);
        }
    }

    auto load_kv = [&](int s) {
        const int jt = s << 6;
        const uint32_t base = sb + (uint32_t)((s % 3) * 16384);
#pragma unroll
        for (int rr = 0; rr < 2; rr++) {
            int ci = tid + 256 * rr;
            int j = ci >> 3, cch = ci & 7;
            cp16(base + (uint32_t)(j * 128 + ((cch ^ (j & 7)) << 4)),
                 Kb + (size_t)(jt + j) * RS + cch * 8);
        }
#pragma unroll
        for (int rr = 0; rr < 2; rr++) {
            int ci = tid + 256 * rr;
            int d = ci >> 3, cch = ci & 7;
            cp16(base + 8192u + (uint32_t)(d * 128 + ((cch ^ (d & 7)) << 4)),
                 Vb + (size_t)d * Nn + jt + cch * 8);
        }
    };

    float o[8][4] = {};
    float osum[4] = {};            // ones-MMA row-sum accumulator (f32, exact)
    char* Pwc = sm + 49152 + wid * 2048;
    const uint32_t sPw = sb + 49152u + (uint32_t)(wid * 2048);

    load_kv(0); CP_COMMIT();
    load_kv(1); CP_COMMIT();

    const int NS = Nn / 64;
    for (int s = 0; s < NS; s++) {
        CP_WAIT1();
        __syncthreads();

        const uint32_t sK = sb + (uint32_t)((s % 3) * 16384);
        const uint32_t sV = sK + 8192u;

        // ---- S = Q @ K^T over this warp's 32-j half ----
        float sc[4][4] = {};
#pragma unroll
        for (int kb = 0; kb < 4; kb++) {
            const int chK = kb * 2 + selK;
#pragma unroll
            for (int ntp = 0; ntp < 2; ntp++) {
                uint32_t b0, b1, b2, b3;
                int j = jh * 32 + ntp * 16 + rowK_l;
                LDMX4(b0, b1, b2, b3,
                      sK + (uint32_t)(j * 128 + ((chK ^ (j & 7)) << 4)));
                mma_f16(sc[2 * ntp],     aq[kb][0], aq[kb][1], aq[kb][2], aq[kb][3], b0, b1);
                mma_f16(sc[2 * ntp + 1], aq[kb][0], aq[kb][1], aq[kb][2], aq[kb][3], b2, b3);
            }
        }

        // prefetch next+1 stage AFTER QK MMAs (LSU burst overlaps softmax/PV)
        if (s + 2 < NS) load_kv(s + 2);
        CP_COMMIT();

        // ---- P = exp2(S) in f16x2 (one MUFU per pair), store fp16 P ----
#pragma unroll
        for (int nt = 0; nt < 4; nt++) {
            uint32_t p01 = ex2_h2(sc[nt][0], sc[nt][1]);
            uint32_t p23 = ex2_h2(sc[nt][2], sc[nt][3]);
            *(uint32_t*)(Pwc + g * 128 + ((nt ^ (g & 7)) << 4) + 4 * q) = p01;
            *(uint32_t*)(Pwc + (g + 8) * 128 + ((nt ^ ((g + 8) & 7)) << 4) + 4 * q) = p23;
        }
        __syncwarp();

        // ---- O += P @ V ; row sums via ones-MMA (B = fp16 1.0) ----
#pragma unroll
        for (int kp = 0; kp < 2; kp++) {
            uint32_t a0, a1, a2, a3;
            const int chP = kp * 2 + selP;
            LDMX4(a0, a1, a2, a3,
                  sPw + (uint32_t)(rowP_l * 128 + ((chP ^ (rowP_l & 7)) << 4)));
            uint32_t b[8][2];
            const int chV = jh * 4 + kp * 2 + selK;
#pragma unroll
            for (int ntp = 0; ntp < 4; ntp++) {
                int d = ntp * 16 + rowK_l;
                LDMX4(b[2 * ntp][0], b[2 * ntp][1], b[2 * ntp + 1][0], b[2 * ntp + 1][1],
                      sV + (uint32_t)(d * 128 + ((chV ^ (d & 7)) << 4)));
            }
#pragma unroll
            for (int nt = 0; nt < 8; nt++)
                mma_f16(o[nt], a0, a1, a2, a3, b[nt][0], b[nt][1]);
            mma_f16(osum, a0, a1, a2, a3, ONES_H2, ONES_H2);  // row sums
        }
    }

    // osum[0] = full row sum (rows g), osum[2] = rows g+8 (j-half partial)
    // ---- merge j-half pairs via (now free) KV stage area ----
    __syncthreads();
    float* Om = (float*)(sm + r * 4096);            // 16x64 f32 per r
    float* Lm = (float*)(sm + 16384) + r * 16;
    if (jh == 1) {
#pragma unroll
        for (int nt = 0; nt < 8; nt++) {
            const int col = nt * 8 + 2 * q;
            Om[g * 64 + col]           = o[nt][0];
            Om[g * 64 + col + 1]       = o[nt][1];
            Om[(g + 8) * 64 + col]     = o[nt][2];
            Om[(g + 8) * 64 + col + 1] = o[nt][3];
        }
        if (q == 0) { Lm[g] = osum[0]; Lm[g + 8] = osum[2]; }
    }
    __syncthreads();
    if (jh == 0) {
        const float inv0 = 1.f / (osum[0] + Lm[g]);
        const float inv1 = 1.f / (osum[2] + Lm[g + 8]);
        __half* out0 = att + (size_t)(bI * Nn + i0 + m0 + g) * INTERc + h * HDc;
        __half* out1 = out0 + 8 * INTERc;
#pragma unroll
        for (int nt = 0; nt < 8; nt++) {
            const int col = nt * 8 + 2 * q;
            *(__half2*)(out0 + col) = __floats2half2_rn(
                (o[nt][0] + Om[g * 64 + col]) * inv0,
                (o[nt][1] + Om[g * 64 + col + 1]) * inv0);
            *(__half2*)(out1 + col) = __floats2half2_rn(
                (o[nt][2] + Om[(g + 8) * 64 + col]) * inv1,
                (o[nt][3] + Om[(g + 8) * 64 + col + 1]) * inv1);
        }
    }
}

// ---------------------------------------------------------------------------
extern "C" void kernel_launch(void* const* d_in, const int* in_sizes, int n_in,
                              void* d_out, int out_size) {
    const float* features = (const float*)d_in[0];
    const float* W_qkv    = (const float*)d_in[1];
    const float* W_out    = (const float*)d_in[2];
    float* out = (float*)d_out;

    __half *feat_h, *wqkvT_h, *woutT_h, *qkv_h, *vT_h, *att_h;
    cudaGetSymbolAddress((void**)&feat_h, g_feat_h);
    cudaGetSymbolAddress((void**)&wqkvT_h, g_wqkvT_h);
    cudaGetSymbolAddress((void**)&woutT_h, g_woutT_h);
    cudaGetSymbolAddress((void**)&qkv_h, g_qkv_h);
    cudaGetSymbolAddress((void**)&vT_h, g_vT_h);
    cudaGetSymbolAddress((void**)&att_h, g_att_h);

    static bool attr_set = false;
    if (!attr_set) {
        cudaFuncSetAttribute(gemm_f16,
                             cudaFuncAttributeMaxDynamicSharedMemorySize, 98304);
        cudaFuncSetAttribute(attn_mma,
                             cudaFuncAttributeMaxDynamicSharedMemorySize, 65536);
        attr_set = true;
    }

    // 0) fp16 casts; weights transposed for n-major B tiles
    {
        int n4 = (Bc * Nn * DIMc) / 4;
        h_cast<<<(n4 + 255) / 256, 256>>>((const float4*)features,
                                          (__half2*)feat_h, n4);
        h_cast_T<<<dim3(3 * INTERc / 32, DIMc / 32), 256>>>(W_qkv, wqkvT_h,
                                                            DIMc, 3 * INTERc);
        h_cast_T<<<dim3(DIMc / 32, INTERc / 32), 256>>>(W_out, woutT_h,
                                                        INTERc, DIMc);
    }

    // 1) QKV projection: Q (scaled) + K -> qkv_h; V -> vT_h (fused transpose)
    dim3 g1(3 * INTERc / 128, Bc * Nn / 128);
    gemm_f16<<<g1, 256, 98304>>>(feat_h, wqkvT_h, qkv_h, nullptr, vT_h,
                                 Bc * Nn, 3 * INTERc, DIMc, 1);

    // 2) MMA attention -> fp16
    dim3 g2(Nn / 64, Bc * HEADc);
    attn_mma<<<g2, 256, 65536>>>(qkv_h, vT_h, att_h);

    // 3) Output projection -> fp32 final
    dim3 g3(DIMc / 128, Bc * Nn / 128);
    gemm_f16<<<g3, 256, 98304>>>(att_h, woutT_h, nullptr, out, nullptr,
                                 Bc * Nn, DIMc, INTERc, 0);
}

// round 13
// speedup vs baseline: 1.0145x; 1.0145x over previous
#include <cuda_runtime.h>
#include <cuda_fp16.h>
#include <math_constants.h>
#include <cstdint>

#define Bc 4
#define Nn 2048
#define DIMc 1024
#define HEADc 16
#define INTERc 1024
#define HDc 64
#define SCALEc 0.03125f   // INTER^-0.5 = 2^-5 (exact)
#define LOG2E 1.4426950408889634f

// Scratch (device globals). *_h buffers hold fp16.
__device__ __align__(16) __half g_feat_h[(size_t)Bc * Nn * DIMc];
__device__ __align__(16) __half g_wqkvT_h[(size_t)3 * INTERc * DIMc];   // W^T
__device__ __align__(16) __half g_woutT_h[(size_t)DIMc * INTERc];       // W^T
__device__ __align__(16) __half g_qkv_h[(size_t)Bc * Nn * 3 * INTERc];  // Q scaled, K
__device__ __align__(16) __half g_vT_h[(size_t)Bc * HEADc * HDc * Nn];  // [bh][d][tok]
__device__ __align__(16) __half g_att_h[(size_t)Bc * Nn * INTERc];

// ---------------------------------------------------------------------------
// Helpers
// ---------------------------------------------------------------------------
__device__ __forceinline__ uint32_t smem_u32(const void* p) {
    uint32_t a;
    asm("{ .reg .u64 t; cvta.to.shared.u64 t, %1; cvt.u32.u64 %0, t; }"
        : "=r"(a) : "l"(p));
    return a;
}
__device__ __forceinline__ float ex2(float x) {
    float y;
    asm("ex2.approx.f32 %0, %1;" : "=f"(y) : "f"(x));
    return y;
}
__device__ __forceinline__ void cp16(uint32_t dst, const void* src) {
    asm volatile("cp.async.cg.shared.global [%0], [%1], 16;"
                 :: "r"(dst), "l"(src));
}
#define CP_COMMIT() asm volatile("cp.async.commit_group;" ::: "memory")
#define CP_WAIT0()  asm volatile("cp.async.wait_group 0;" ::: "memory")
#define CP_WAIT1()  asm volatile("cp.async.wait_group 1;" ::: "memory")

#define LDMX4(r0, r1, r2, r3, addr) \
    asm volatile("ldmatrix.sync.aligned.m8n8.x4.shared.b16 {%0,%1,%2,%3}, [%4];" \
                 : "=r"(r0), "=r"(r1), "=r"(r2), "=r"(r3) : "r"(addr))

__device__ __forceinline__ void mma_f16(float c[4],
                                        uint32_t a0, uint32_t a1, uint32_t a2, uint32_t a3,
                                        uint32_t b0, uint32_t b1) {
    asm volatile("mma.sync.aligned.m16n8k16.row.col.f32.f16.f16.f32 "
                 "{%0,%1,%2,%3}, {%4,%5,%6,%7}, {%8,%9}, {%0,%1,%2,%3};"
                 : "+f"(c[0]), "+f"(c[1]), "+f"(c[2]), "+f"(c[3])
                 : "r"(a0), "r"(a1), "r"(a2), "r"(a3), "r"(b0), "r"(b1));
}

// ---------------------------------------------------------------------------
// fp16 casts
// ---------------------------------------------------------------------------
__global__ void h_cast(const float4* __restrict__ in, __half2* __restrict__ out,
                       int n4) {
    int i = blockIdx.x * blockDim.x + threadIdx.x;
    if (i < n4) {
        float4 v = in[i];
        out[2 * i]     = __floats2half2_rn(v.x, v.y);
        out[2 * i + 1] = __floats2half2_rn(v.z, v.w);
    }
}

// in: [K][N] f32, out: [N][K] fp16
__global__ void h_cast_T(const float* __restrict__ in, __half* __restrict__ out,
                         int K, int N) {
    __shared__ float t[32][33];
    const int n0 = blockIdx.x << 5, k0 = blockIdx.y << 5;
    const int c = threadIdx.x & 31, r4 = threadIdx.x >> 5;
#pragma unroll
    for (int rr = 0; rr < 32; rr += 8)
        t[r4 + rr][c] = in[(size_t)(k0 + r4 + rr) * N + n0 + c];
    __syncthreads();
#pragma unroll
    for (int rr = 0; rr < 32; rr += 8)
        out[(size_t)(n0 + r4 + rr) * K + k0 + c] = __float2half_rn(t[c][r4 + rr]);
}

// ---------------------------------------------------------------------------
// fp16 mma.sync GEMM (unchanged from R11): CTA 128x128, BK=64, 3-stage.
// ---------------------------------------------------------------------------
__global__ __launch_bounds__(256, 2)
void gemm_f16(const __half* __restrict__ A, const __half* __restrict__ Bt,
              __half* __restrict__ Ch, float* __restrict__ Cf,
              __half* __restrict__ vT, int M, int Nc, int K, int mode) {
    extern __shared__ char sm[];
    const uint32_t sb = smem_u32(sm);
    const int tid = threadIdx.x;
    const int wid = tid >> 5, lane = tid & 31;
    const int g = lane >> 2, q = lane & 3;
    const int warp_m = wid >> 1;
    const int warp_n = wid & 1;
    const int brow = blockIdx.y << 7;
    const int bcol = blockIdx.x << 7;
    const int NS = K >> 6;

    const int rowA_l = lane & 15;
    const int selA   = lane >> 4;
    const int rowB_l = (lane & 7) + ((lane >> 4) << 3);
    const int selB   = (lane >> 3) & 1;

    auto load_stage = [&](int s) {
        const int k0 = s << 6;
        uint32_t base = sb + (uint32_t)((s % 3) * 32768);
#pragma unroll
        for (int r = 0; r < 4; r++) {
            int ci = tid + 256 * r;
            int m = ci >> 3, kc = ci & 7;
            cp16(base + (uint32_t)(m * 128 + ((kc ^ (m & 7)) << 4)),
                 A + (size_t)(brow + m) * K + k0 + kc * 8);
        }
#pragma unroll
        for (int r = 0; r < 4; r++) {
            int ci = tid + 256 * r;
            int n = ci >> 3, kc = ci & 7;
            cp16(base + 16384u + (uint32_t)(n * 128 + ((kc ^ (n & 7)) << 4)),
                 Bt + (size_t)(bcol + n) * K + k0 + kc * 8);
        }
    };

    float c[2][8][4] = {};

    load_stage(0); CP_COMMIT();
    load_stage(1); CP_COMMIT();

    for (int s = 0; s < NS; s++) {
        CP_WAIT1();
        __syncthreads();

        const uint32_t sA = sb + (uint32_t)((s % 3) * 32768);
        const uint32_t sB = sA + 16384u;

#pragma unroll
        for (int kk = 0; kk < 4; kk++) {
            uint32_t a[2][4];
            const int chA = kk * 2 + selA;
#pragma unroll
            for (int mt = 0; mt < 2; mt++) {
                int row = warp_m * 32 + mt * 16 + rowA_l;
                LDMX4(a[mt][0], a[mt][1], a[mt][2], a[mt][3],
                      sA + (uint32_t)(row * 128 + ((chA ^ (row & 7)) << 4)));
            }
            uint32_t b[8][2];
            const int chB = kk * 2 + selB;
#pragma unroll
            for (int ntp = 0; ntp < 4; ntp++) {
                int row = warp_n * 64 + ntp * 16 + rowB_l;
                LDMX4(b[2 * ntp][0], b[2 * ntp][1], b[2 * ntp + 1][0], b[2 * ntp + 1][1],
                      sB + (uint32_t)(row * 128 + ((chB ^ (row & 7)) << 4)));
            }
#pragma unroll
            for (int mt = 0; mt < 2; mt++)
#pragma unroll
                for (int nt = 0; nt < 8; nt++)
                    mma_f16(c[mt][nt], a[mt][0], a[mt][1], a[mt][2], a[mt][3],
                            b[nt][0], b[nt][1]);
            if (kk == 0) {
                if (s + 2 < NS) load_stage(s + 2);
                CP_COMMIT();
            }
        }
    }

    if (mode && bcol >= 2 * INTERc) {
#pragma unroll
        for (int mt = 0; mt < 2; mt++) {
#pragma unroll
            for (int nt = 0; nt < 8; nt++) {
                int row = brow + warp_m * 32 + mt * 16 + g;
                int col = bcol - 2 * INTERc + warp_n * 64 + nt * 8 + q * 2;
                int bI = row >> 11, tok = row & 2047;
                int h = col >> 6, d = col & 63;
                __half* base = vT + (((size_t)(bI * 16 + h) * 64 + d) * Nn) + tok;
                base[0]      = __float2half_rn(c[mt][nt][0]);
                base[Nn]     = __float2half_rn(c[mt][nt][1]);
                base[8]      = __float2half_rn(c[mt][nt][2]);
                base[Nn + 8] = __float2half_rn(c[mt][nt][3]);
            }
        }
    } else if (mode) {
        const float fs = (bcol < INTERc) ? (SCALEc * LOG2E) : 1.0f;
#pragma unroll
        for (int mt = 0; mt < 2; mt++) {
#pragma unroll
            for (int nt = 0; nt < 8; nt++) {
                int row = brow + warp_m * 32 + mt * 16 + g;
                int col = bcol + warp_n * 64 + nt * 8 + q * 2;
                *(__half2*)(Ch + (size_t)row * Nc + col) =
                    __floats2half2_rn(c[mt][nt][0] * fs, c[mt][nt][1] * fs);
                *(__half2*)(Ch + (size_t)(row + 8) * Nc + col) =
                    __floats2half2_rn(c[mt][nt][2] * fs, c[mt][nt][3] * fs);
            }
        }
    } else {
#pragma unroll
        for (int mt = 0; mt < 2; mt++) {
#pragma unroll
            for (int nt = 0; nt < 8; nt++) {
                int row = brow + warp_m * 32 + mt * 16 + g;
                int col = bcol + warp_n * 64 + nt * 8 + q * 2;
                *(float2*)(Cf + (size_t)row * Nc + col) =
                    make_float2(c[mt][nt][0], c[mt][nt][1]);
                *(float2*)(Cf + (size_t)(row + 8) * Nc + col) =
                    make_float2(c[mt][nt][2], c[mt][nt][3]);
            }
        }
    }
}

// ---------------------------------------------------------------------------
// fp16 MMA flash attention, 128-key stages (NS=16), 2-stage pipeline.
// CTA = 64 Q rows x (b,h). Warp (r, jh): rows r*16..r*16+15, j-half = 64 keys.
// Per warp/stage: 32 QK MMA + 32 exp + 32 PV MMA. Softmax = R10 form.
// Smem: 2 x (K 16KB + V 16KB) + per-warp P 2KB x8 = 80KB.
// ---------------------------------------------------------------------------
__global__ __launch_bounds__(256, 2)
void attn_mma(const __half* __restrict__ qkv, const __half* __restrict__ vT,
              __half* __restrict__ att) {
    extern __shared__ char sm[];
    const uint32_t sb = smem_u32(sm);
    const int tid = threadIdx.x;
    const int wid = tid >> 5, lane = tid & 31;
    const int g = lane >> 2, q = lane & 3;
    const int r = wid >> 1, jh = wid & 1;
    const int bh = blockIdx.y;
    const int bI = bh >> 4, h = bh & 15;
    const int i0 = blockIdx.x << 6;
    const int m0 = r << 4;

    const int rowK_l = (lane & 7) + ((lane >> 4) << 3);
    const int selK   = (lane >> 3) & 1;
    const int rowP_l = lane & 15;
    const int selP   = lane >> 4;

    const size_t RS = 3 * INTERc;
    const __half* Qb = qkv + (size_t)(bI * Nn) * RS + h * HDc;
    const __half* Kb = Qb + INTERc;
    const __half* Vb = vT + (size_t)bh * HDc * Nn;

    uint32_t aq[4][4];
    {
        const __half* q0 = Qb + (size_t)(i0 + m0 + g) * RS;
        const __half* q1 = Qb + (size_t)(i0 + m0 + g + 8) * RS;
#pragma unroll
        for (int kb = 0; kb < 4; kb++) {
            aq[kb][0] = *(const uint32_t*)(q0 + kb * 16 + 2 * q);
            aq[kb][1] = *(const uint32_t*)(q1 + kb * 16 + 2 * q);
            aq[kb][2] = *(const uint32_t*)(q0 + kb * 16 + 2 * q + 8);
            aq[kb][3] = *(const uint32_t*)(q1 + kb * 16 + 2 * q + 8);
        }
    }

    // Stage = 128 keys. K tile [128 j][64 d] (128B rows, 8 chunks, ^(j&7));
    // V tile [64 d][128 j] (256B rows, 16 chunks, ^(d&15)).
    auto load_kv = [&](int s) {
        const int jt = s << 7;
        const uint32_t base = sb + (uint32_t)((s & 1) * 32768);
#pragma unroll
        for (int rr = 0; rr < 4; rr++) {
            int ci = tid + 256 * rr;
            int j = ci >> 3, cch = ci & 7;
            cp16(base + (uint32_t)(j * 128 + ((cch ^ (j & 7)) << 4)),
                 Kb + (size_t)(jt + j) * RS + cch * 8);
        }
#pragma unroll
        for (int rr = 0; rr < 4; rr++) {
            int ci = tid + 256 * rr;
            int d = ci >> 4, cch = ci & 15;
            cp16(base + 16384u + (uint32_t)(d * 256 + ((cch ^ (d & 15)) << 4)),
                 Vb + (size_t)d * Nn + jt + cch * 8);
        }
    };

    float o[8][4] = {};
    float lrow0 = 0.f, lrow1 = 0.f;
    char* Pwc = sm + 65536 + wid * 2048;
    const uint32_t sPw = sb + 65536u + (uint32_t)(wid * 2048);

    load_kv(0); CP_COMMIT();

    const int NS = Nn / 128;
    for (int s = 0; s < NS; s++) {
        CP_WAIT0();
        __syncthreads();

        const uint32_t sK = sb + (uint32_t)((s & 1) * 32768);
        const uint32_t sV = sK + 16384u;

        // ---- S = Q @ K^T over this warp's 64-j half ----
        float sc[8][4] = {};
#pragma unroll
        for (int kb = 0; kb < 4; kb++) {
            const int chK = kb * 2 + selK;
#pragma unroll
            for (int ntp = 0; ntp < 4; ntp++) {
                uint32_t b0, b1, b2, b3;
                int j = jh * 64 + ntp * 16 + rowK_l;
                LDMX4(b0, b1, b2, b3,
                      sK + (uint32_t)(j * 128 + ((chK ^ (j & 7)) << 4)));
                mma_f16(sc[2 * ntp],     aq[kb][0], aq[kb][1], aq[kb][2], aq[kb][3], b0, b1);
                mma_f16(sc[2 * ntp + 1], aq[kb][0], aq[kb][1], aq[kb][2], aq[kb][3], b2, b3);
            }
        }

        // prefetch next stage (opposite buffer, freed by the barrier above)
        if (s + 1 < NS) { load_kv(s + 1); CP_COMMIT(); }

        // ---- P = exp2(S), partial row sums (f32) ----
        float sum0 = 0.f, sum1 = 0.f;
#pragma unroll
        for (int nt = 0; nt < 8; nt++) {
            sc[nt][0] = ex2(sc[nt][0]);
            sc[nt][1] = ex2(sc[nt][1]);
            sc[nt][2] = ex2(sc[nt][2]);
            sc[nt][3] = ex2(sc[nt][3]);
            sum0 += sc[nt][0] + sc[nt][1];
            sum1 += sc[nt][2] + sc[nt][3];
        }
        lrow0 += sum0;
        lrow1 += sum1;

        // ---- P (fp16) -> per-warp smem 16x64, 128B rows, chunk nt^(row&7) ----
#pragma unroll
        for (int nt = 0; nt < 8; nt++) {
            *(__half2*)(Pwc + g * 128 + ((nt ^ (g & 7)) << 4) + 4 * q) =
                __floats2half2_rn(sc[nt][0], sc[nt][1]);
            *(__half2*)(Pwc + (g + 8) * 128 + ((nt ^ ((g + 8) & 7)) << 4) + 4 * q) =
                __floats2half2_rn(sc[nt][2], sc[nt][3]);
        }
        __syncwarp();

        // ---- O += P @ V over this warp's j half (4 k-steps of 16) ----
#pragma unroll
        for (int kp = 0; kp < 4; kp++) {
            uint32_t a0, a1, a2, a3;
            const int chP = kp * 2 + selP;
            LDMX4(a0, a1, a2, a3,
                  sPw + (uint32_t)(rowP_l * 128 + ((chP ^ (rowP_l & 7)) << 4)));
            uint32_t b[8][2];
            const int chV = jh * 8 + kp * 2 + selK;
#pragma unroll
            for (int ntp = 0; ntp < 4; ntp++) {
                int d = ntp * 16 + rowK_l;
                LDMX4(b[2 * ntp][0], b[2 * ntp][1], b[2 * ntp + 1][0], b[2 * ntp + 1][1],
                      sV + (uint32_t)(d * 256 + ((chV ^ (d & 15)) << 4)));
            }
#pragma unroll
            for (int nt = 0; nt < 8; nt++)
                mma_f16(o[nt], a0, a1, a2, a3, b[nt][0], b[nt][1]);
        }
    }

    // reduce partial row sums over the 4 q-lanes
#pragma unroll
    for (int of = 1; of <= 2; of <<= 1) {
        lrow0 += __shfl_xor_sync(0xffffffffu, lrow0, of);
        lrow1 += __shfl_xor_sync(0xffffffffu, lrow1, of);
    }

    // ---- merge j-half pairs via (now free) KV stage area ----
    __syncthreads();
    float* Om = (float*)(sm + r * 4096);
    float* Lm = (float*)(sm + 16384) + r * 16;
    if (jh == 1) {
#pragma unroll
        for (int nt = 0; nt < 8; nt++) {
            const int col = nt * 8 + 2 * q;
            Om[g * 64 + col]           = o[nt][0];
            Om[g * 64 + col + 1]       = o[nt][1];
            Om[(g + 8) * 64 + col]     = o[nt][2];
            Om[(g + 8) * 64 + col + 1] = o[nt][3];
        }
        if (q == 0) { Lm[g] = lrow0; Lm[g + 8] = lrow1; }
    }
    __syncthreads();
    if (jh == 0) {
        const float inv0 = 1.f / (lrow0 + Lm[g]);
        const float inv1 = 1.f / (lrow1 + Lm[g + 8]);
        __half* out0 = att + (size_t)(bI * Nn + i0 + m0 + g) * INTERc + h * HDc;
        __half* out1 = out0 + 8 * INTERc;
#pragma unroll
        for (int nt = 0; nt < 8; nt++) {
            const int col = nt * 8 + 2 * q;
            *(__half2*)(out0 + col) = __floats2half2_rn(
                (o[nt][0] + Om[g * 64 + col]) * inv0,
                (o[nt][1] + Om[g * 64 + col + 1]) * inv0);
            *(__half2*)(out1 + col) = __floats2half2_rn(
                (o[nt][2] + Om[(g + 8) * 64 + col]) * inv1,
                (o[nt][3] + Om[(g + 8) * 64 + col + 1]) * inv1);
        }
    }
}

// ---------------------------------------------------------------------------
extern "C" void kernel_launch(void* const* d_in, const int* in_sizes, int n_in,
                              void* d_out, int out_size) {
    const float* features = (const float*)d_in[0];
    const float* W_qkv    = (const float*)d_in[1];
    const float* W_out    = (const float*)d_in[2];
    float* out = (float*)d_out;

    __half *feat_h, *wqkvT_h, *woutT_h, *qkv_h, *vT_h, *att_h;
    cudaGetSymbolAddress((void**)&feat_h, g_feat_h);
    cudaGetSymbolAddress((void**)&wqkvT_h, g_wqkvT_h);
    cudaGetSymbolAddress((void**)&woutT_h, g_woutT_h);
    cudaGetSymbolAddress((void**)&qkv_h, g_qkv_h);
    cudaGetSymbolAddress((void**)&vT_h, g_vT_h);
    cudaGetSymbolAddress((void**)&att_h, g_att_h);

    static bool attr_set = false;
    if (!attr_set) {
        cudaFuncSetAttribute(gemm_f16,
                             cudaFuncAttributeMaxDynamicSharedMemorySize, 98304);
        cudaFuncSetAttribute(attn_mma,
                             cudaFuncAttributeMaxDynamicSharedMemorySize, 81920);
        attr_set = true;
    }

    // 0) fp16 casts; weights transposed for n-major B tiles
    {
        int n4 = (Bc * Nn * DIMc) / 4;
        h_cast<<<(n4 + 255) / 256, 256>>>((const float4*)features,
                                          (__half2*)feat_h, n4);
        h_cast_T<<<dim3(3 * INTERc / 32, DIMc / 32), 256>>>(W_qkv, wqkvT_h,
                                                            DIMc, 3 * INTERc);
        h_cast_T<<<dim3(DIMc / 32, INTERc / 32), 256>>>(W_out, woutT_h,
                                                        INTERc, DIMc);
    }

    // 1) QKV projection: Q (scaled) + K -> qkv_h; V -> vT_h (fused transpose)
    dim3 g1(3 * INTERc / 128, Bc * Nn / 128);
    gemm_f16<<<g1, 256, 98304>>>(feat_h, wqkvT_h, qkv_h, nullptr, vT_h,
                                 Bc * Nn, 3 * INTERc, DIMc, 1);

    // 2) MMA attention -> fp16
    dim3 g2(Nn / 64, Bc * HEADc);
    attn_mma<<<g2, 256, 81920>>>(qkv_h, vT_h, att_h);

    // 3) Output projection -> fp32 final
    dim3 g3(DIMc / 128, Bc * Nn / 128);
    gemm_f16<<<g3, 256, 98304>>>(att_h, woutT_h, nullptr, out, nullptr,
                                 Bc * Nn, DIMc, INTERc, 0);
}

// round 14
// speedup vs baseline: 1.0643x; 1.0490x over previous
#include <cuda_runtime.h>
#include <cuda_fp16.h>
#include <math_constants.h>
#include <cstdint>

#define Bc 4
#define Nn 2048
#define DIMc 1024
#define HEADc 16
#define INTERc 1024
#define HDc 64
#define SCALEc 0.03125f   // INTER^-0.5 = 2^-5 (exact)
#define LOG2E 1.4426950408889634f

// Scratch (device globals). *_h buffers hold fp16.
__device__ __align__(16) __half g_feat_h[(size_t)Bc * Nn * DIMc];
__device__ __align__(16) __half g_wqkvT_h[(size_t)3 * INTERc * DIMc];   // W^T
__device__ __align__(16) __half g_woutT_h[(size_t)DIMc * INTERc];       // W^T
__device__ __align__(16) __half g_qkv_h[(size_t)Bc * Nn * 3 * INTERc];  // Q scaled, K
__device__ __align__(16) __half g_vT_h[(size_t)Bc * HEADc * HDc * Nn];  // [bh][d][tok]
__device__ __align__(16) __half g_att_h[(size_t)Bc * Nn * INTERc];

// ---------------------------------------------------------------------------
// Helpers
// ---------------------------------------------------------------------------
__device__ __forceinline__ uint32_t smem_u32(const void* p) {
    uint32_t a;
    asm("{ .reg .u64 t; cvta.to.shared.u64 t, %1; cvt.u32.u64 %0, t; }"
        : "=r"(a) : "l"(p));
    return a;
}
// pack two f32 -> f16x2 {lo, hi}, exp2 both halves in ONE MUFU
__device__ __forceinline__ uint32_t ex2_h2(float lo, float hi) {
    uint32_t p;
    asm("cvt.rn.f16x2.f32 %0, %1, %2;" : "=r"(p) : "f"(hi), "f"(lo));
    asm("ex2.approx.f16x2 %0, %0;" : "+r"(p));
    return p;
}
__device__ __forceinline__ void cp16(uint32_t dst, const void* src) {
    asm volatile("cp.async.cg.shared.global [%0], [%1], 16;"
                 :: "r"(dst), "l"(src));
}
#define CP_COMMIT() asm volatile("cp.async.commit_group;" ::: "memory")
#define CP_WAIT0()  asm volatile("cp.async.wait_group 0;" ::: "memory")
#define CP_WAIT1()  asm volatile("cp.async.wait_group 1;" ::: "memory")

#define LDMX4(r0, r1, r2, r3, addr) \
    asm volatile("ldmatrix.sync.aligned.m8n8.x4.shared.b16 {%0,%1,%2,%3}, [%4];" \
                 : "=r"(r0), "=r"(r1), "=r"(r2), "=r"(r3) : "r"(addr))

__device__ __forceinline__ void mma_f16(float c[4],
                                        uint32_t a0, uint32_t a1, uint32_t a2, uint32_t a3,
                                        uint32_t b0, uint32_t b1) {
    asm volatile("mma.sync.aligned.m16n8k16.row.col.f32.f16.f16.f32 "
                 "{%0,%1,%2,%3}, {%4,%5,%6,%7}, {%8,%9}, {%0,%1,%2,%3};"
                 : "+f"(c[0]), "+f"(c[1]), "+f"(c[2]), "+f"(c[3])
                 : "r"(a0), "r"(a1), "r"(a2), "r"(a3), "r"(b0), "r"(b1));
}

// ---------------------------------------------------------------------------
// fp16 casts
// ---------------------------------------------------------------------------
__global__ void h_cast(const float4* __restrict__ in, __half2* __restrict__ out,
                       int n4) {
    int i = blockIdx.x * blockDim.x + threadIdx.x;
    if (i < n4) {
        float4 v = in[i];
        out[2 * i]     = __floats2half2_rn(v.x, v.y);
        out[2 * i + 1] = __floats2half2_rn(v.z, v.w);
    }
}

// in: [K][N] f32, out: [N][K] fp16
__global__ void h_cast_T(const float* __restrict__ in, __half* __restrict__ out,
                         int K, int N) {
    __shared__ float t[32][33];
    const int n0 = blockIdx.x << 5, k0 = blockIdx.y << 5;
    const int c = threadIdx.x & 31, r4 = threadIdx.x >> 5;
#pragma unroll
    for (int rr = 0; rr < 32; rr += 8)
        t[r4 + rr][c] = in[(size_t)(k0 + r4 + rr) * N + n0 + c];
    __syncthreads();
#pragma unroll
    for (int rr = 0; rr < 32; rr += 8)
        out[(size_t)(n0 + r4 + rr) * K + k0 + c] = __float2half_rn(t[c][r4 + rr]);
}

// ---------------------------------------------------------------------------
// fp16 mma.sync GEMM (unchanged): CTA 128x128, BK=64, 3-stage.
// ---------------------------------------------------------------------------
__global__ __launch_bounds__(256, 2)
void gemm_f16(const __half* __restrict__ A, const __half* __restrict__ Bt,
              __half* __restrict__ Ch, float* __restrict__ Cf,
              __half* __restrict__ vT, int M, int Nc, int K, int mode) {
    extern __shared__ char sm[];
    const uint32_t sb = smem_u32(sm);
    const int tid = threadIdx.x;
    const int wid = tid >> 5, lane = tid & 31;
    const int g = lane >> 2, q = lane & 3;
    const int warp_m = wid >> 1;
    const int warp_n = wid & 1;
    const int brow = blockIdx.y << 7;
    const int bcol = blockIdx.x << 7;
    const int NS = K >> 6;

    const int rowA_l = lane & 15;
    const int selA   = lane >> 4;
    const int rowB_l = (lane & 7) + ((lane >> 4) << 3);
    const int selB   = (lane >> 3) & 1;

    auto load_stage = [&](int s) {
        const int k0 = s << 6;
        uint32_t base = sb + (uint32_t)((s % 3) * 32768);
#pragma unroll
        for (int r = 0; r < 4; r++) {
            int ci = tid + 256 * r;
            int m = ci >> 3, kc = ci & 7;
            cp16(base + (uint32_t)(m * 128 + ((kc ^ (m & 7)) << 4)),
                 A + (size_t)(brow + m) * K + k0 + kc * 8);
        }
#pragma unroll
        for (int r = 0; r < 4; r++) {
            int ci = tid + 256 * r;
            int n = ci >> 3, kc = ci & 7;
            cp16(base + 16384u + (uint32_t)(n * 128 + ((kc ^ (n & 7)) << 4)),
                 Bt + (size_t)(bcol + n) * K + k0 + kc * 8);
        }
    };

    float c[2][8][4] = {};

    load_stage(0); CP_COMMIT();
    load_stage(1); CP_COMMIT();

    for (int s = 0; s < NS; s++) {
        CP_WAIT1();
        __syncthreads();

        const uint32_t sA = sb + (uint32_t)((s % 3) * 32768);
        const uint32_t sB = sA + 16384u;

#pragma unroll
        for (int kk = 0; kk < 4; kk++) {
            uint32_t a[2][4];
            const int chA = kk * 2 + selA;
#pragma unroll
            for (int mt = 0; mt < 2; mt++) {
                int row = warp_m * 32 + mt * 16 + rowA_l;
                LDMX4(a[mt][0], a[mt][1], a[mt][2], a[mt][3],
                      sA + (uint32_t)(row * 128 + ((chA ^ (row & 7)) << 4)));
            }
            uint32_t b[8][2];
            const int chB = kk * 2 + selB;
#pragma unroll
            for (int ntp = 0; ntp < 4; ntp++) {
                int row = warp_n * 64 + ntp * 16 + rowB_l;
                LDMX4(b[2 * ntp][0], b[2 * ntp][1], b[2 * ntp + 1][0], b[2 * ntp + 1][1],
                      sB + (uint32_t)(row * 128 + ((chB ^ (row & 7)) << 4)));
            }
#pragma unroll
            for (int mt = 0; mt < 2; mt++)
#pragma unroll
                for (int nt = 0; nt < 8; nt++)
                    mma_f16(c[mt][nt], a[mt][0], a[mt][1], a[mt][2], a[mt][3],
                            b[nt][0], b[nt][1]);
            if (kk == 0) {
                if (s + 2 < NS) load_stage(s + 2);
                CP_COMMIT();
            }
        }
    }

    if (mode && bcol >= 2 * INTERc) {
#pragma unroll
        for (int mt = 0; mt < 2; mt++) {
#pragma unroll
            for (int nt = 0; nt < 8; nt++) {
                int row = brow + warp_m * 32 + mt * 16 + g;
                int col = bcol - 2 * INTERc + warp_n * 64 + nt * 8 + q * 2;
                int bI = row >> 11, tok = row & 2047;
                int h = col >> 6, d = col & 63;
                __half* base = vT + (((size_t)(bI * 16 + h) * 64 + d) * Nn) + tok;
                base[0]      = __float2half_rn(c[mt][nt][0]);
                base[Nn]     = __float2half_rn(c[mt][nt][1]);
                base[8]      = __float2half_rn(c[mt][nt][2]);
                base[Nn + 8] = __float2half_rn(c[mt][nt][3]);
            }
        }
    } else if (mode) {
        const float fs = (bcol < INTERc) ? (SCALEc * LOG2E) : 1.0f;
#pragma unroll
        for (int mt = 0; mt < 2; mt++) {
#pragma unroll
            for (int nt = 0; nt < 8; nt++) {
                int row = brow + warp_m * 32 + mt * 16 + g;
                int col = bcol + warp_n * 64 + nt * 8 + q * 2;
                *(__half2*)(Ch + (size_t)row * Nc + col) =
                    __floats2half2_rn(c[mt][nt][0] * fs, c[mt][nt][1] * fs);
                *(__half2*)(Ch + (size_t)(row + 8) * Nc + col) =
                    __floats2half2_rn(c[mt][nt][2] * fs, c[mt][nt][3] * fs);
            }
        }
    } else {
#pragma unroll
        for (int mt = 0; mt < 2; mt++) {
#pragma unroll
            for (int nt = 0; nt < 8; nt++) {
                int row = brow + warp_m * 32 + mt * 16 + g;
                int col = bcol + warp_n * 64 + nt * 8 + q * 2;
                *(float2*)(Cf + (size_t)row * Nc + col) =
                    make_float2(c[mt][nt][0], c[mt][nt][1]);
                *(float2*)(Cf + (size_t)(row + 8) * Nc + col) =
                    make_float2(c[mt][nt][2], c[mt][nt][3]);
            }
        }
    }
}

// ---------------------------------------------------------------------------
// fp16 MMA flash attention, 32-row warps (K/V frag reuse x2).
// CTA = 64 Q rows x (b,h), 4 warps (128 thr). Warp (r, jh): rows r*32..+31,
// j-half = 64 of 128 keys/stage. Per warp/stage: 64 QK MMA + 64 PV MMA with
// only 16+16 K/V LDSM (~160B shared traffic per MMA, was 288B).
// exp via ex2.f16x2; row sums f32 from quantized P (consistent normalization).
// Smem: 2 x (K 16KB + V 16KB) + 4 x P 4KB = 80KB. 2 CTAs/SM.
// ---------------------------------------------------------------------------
__global__ __launch_bounds__(128, 2)
void attn_mma(const __half* __restrict__ qkv, const __half* __restrict__ vT,
              __half* __restrict__ att) {
    extern __shared__ char sm[];
    const uint32_t sb = smem_u32(sm);
    const int tid = threadIdx.x;
    const int wid = tid >> 5, lane = tid & 31;
    const int g = lane >> 2, q = lane & 3;
    const int r = wid >> 1, jh = wid & 1;
    const int bh = blockIdx.y;
    const int bI = bh >> 4, h = bh & 15;
    const int i0 = blockIdx.x << 6;
    const int m0 = r << 5;   // 32 rows per warp

    const int rowK_l = (lane & 7) + ((lane >> 4) << 3);
    const int selK   = (lane >> 3) & 1;
    const int rowP_l = lane & 15;
    const int selP   = lane >> 4;

    const size_t RS = 3 * INTERc;
    const __half* Qb = qkv + (size_t)(bI * Nn) * RS + h * HDc;
    const __half* Kb = Qb + INTERc;
    const __half* Vb = vT + (size_t)bh * HDc * Nn;

    // Q fragments: 2 m-tiles x 4 k-steps (Q pre-scaled by SCALE*log2e)
    uint32_t aq[2][4][4];
#pragma unroll
    for (int mt = 0; mt < 2; mt++) {
        const __half* q0 = Qb + (size_t)(i0 + m0 + mt * 16 + g) * RS;
        const __half* q1 = q0 + 8 * RS;
#pragma unroll
        for (int kb = 0; kb < 4; kb++) {
            aq[mt][kb][0] = *(const uint32_t*)(q0 + kb * 16 + 2 * q);
            aq[mt][kb][1] = *(const uint32_t*)(q1 + kb * 16 + 2 * q);
            aq[mt][kb][2] = *(const uint32_t*)(q0 + kb * 16 + 2 * q + 8);
            aq[mt][kb][3] = *(const uint32_t*)(q1 + kb * 16 + 2 * q + 8);
        }
    }

    // Stage = 128 keys. K [128 j][64 d] 128B rows ^(j&7); V [64 d][128 j]
    // 256B rows ^(d&15). 128 threads -> 8 chunks each per tile.
    auto load_kv = [&](int s) {
        const int jt = s << 7;
        const uint32_t base = sb + (uint32_t)((s & 1) * 32768);
#pragma unroll
        for (int rr = 0; rr < 8; rr++) {
            int ci = tid + 128 * rr;
            int j = ci >> 3, cch = ci & 7;
            cp16(base + (uint32_t)(j * 128 + ((cch ^ (j & 7)) << 4)),
                 Kb + (size_t)(jt + j) * RS + cch * 8);
        }
#pragma unroll
        for (int rr = 0; rr < 8; rr++) {
            int ci = tid + 128 * rr;
            int d = ci >> 4, cch = ci & 15;
            cp16(base + 16384u + (uint32_t)(d * 256 + ((cch ^ (d & 15)) << 4)),
                 Vb + (size_t)d * Nn + jt + cch * 8);
        }
    };

    float o[2][8][4] = {};
    float lrow[2][2] = {};
    char* Pwc = sm + 65536 + wid * 4096;   // 32 rows x 128B
    const uint32_t sPw = sb + 65536u + (uint32_t)(wid * 4096);

    load_kv(0); CP_COMMIT();

    const int NS = Nn / 128;
    for (int s = 0; s < NS; s++) {
        CP_WAIT0();
        __syncthreads();

        const uint32_t sK = sb + (uint32_t)((s & 1) * 32768);
        const uint32_t sV = sK + 16384u;

        // ---- S = Q @ K^T : K frags shared across both m-tiles ----
        float sc[2][8][4] = {};
#pragma unroll
        for (int kb = 0; kb < 4; kb++) {
            const int chK = kb * 2 + selK;
#pragma unroll
            for (int ntp = 0; ntp < 4; ntp++) {
                uint32_t b0, b1, b2, b3;
                int j = jh * 64 + ntp * 16 + rowK_l;
                LDMX4(b0, b1, b2, b3,
                      sK + (uint32_t)(j * 128 + ((chK ^ (j & 7)) << 4)));
#pragma unroll
                for (int mt = 0; mt < 2; mt++) {
                    mma_f16(sc[mt][2 * ntp],     aq[mt][kb][0], aq[mt][kb][1],
                            aq[mt][kb][2], aq[mt][kb][3], b0, b1);
                    mma_f16(sc[mt][2 * ntp + 1], aq[mt][kb][0], aq[mt][kb][1],
                            aq[mt][kb][2], aq[mt][kb][3], b2, b3);
                }
            }
        }

        // prefetch next stage
        if (s + 1 < NS) { load_kv(s + 1); CP_COMMIT(); }

        // ---- P = exp2(S) (f16x2 MUFU); sums f32 from quantized P ----
#pragma unroll
        for (int mt = 0; mt < 2; mt++) {
            const int row0 = mt * 16 + g, row1 = row0 + 8;
            float s0 = 0.f, s1 = 0.f;
#pragma unroll
            for (int nt = 0; nt < 8; nt++) {
                uint32_t p01 = ex2_h2(sc[mt][nt][0], sc[mt][nt][1]);
                uint32_t p23 = ex2_h2(sc[mt][nt][2], sc[mt][nt][3]);
                *(uint32_t*)(Pwc + row0 * 128 + ((nt ^ (row0 & 7)) << 4) + 4 * q) = p01;
                *(uint32_t*)(Pwc + row1 * 128 + ((nt ^ (row1 & 7)) << 4) + 4 * q) = p23;
                float2 f01 = __half22float2(*(__half2*)&p01);
                float2 f23 = __half22float2(*(__half2*)&p23);
                s0 += f01.x + f01.y;
                s1 += f23.x + f23.y;
            }
            lrow[mt][0] += s0;
            lrow[mt][1] += s1;
        }
        __syncwarp();

        // ---- O += P @ V : V frags shared across both m-tiles ----
#pragma unroll
        for (int kp = 0; kp < 4; kp++) {
            uint32_t a[2][4];
            const int chP = kp * 2 + selP;
#pragma unroll
            for (int mt = 0; mt < 2; mt++) {
                int rowP = mt * 16 + rowP_l;
                LDMX4(a[mt][0], a[mt][1], a[mt][2], a[mt][3],
                      sPw + (uint32_t)(rowP * 128 + ((chP ^ (rowP & 7)) << 4)));
            }
            uint32_t b[8][2];
            const int chV = jh * 8 + kp * 2 + selK;
#pragma unroll
            for (int ntp = 0; ntp < 4; ntp++) {
                int d = ntp * 16 + rowK_l;
                LDMX4(b[2 * ntp][0], b[2 * ntp][1], b[2 * ntp + 1][0], b[2 * ntp + 1][1],
                      sV + (uint32_t)(d * 256 + ((chV ^ (d & 15)) << 4)));
            }
#pragma unroll
            for (int mt = 0; mt < 2; mt++)
#pragma unroll
                for (int nt = 0; nt < 8; nt++)
                    mma_f16(o[mt][nt], a[mt][0], a[mt][1], a[mt][2], a[mt][3],
                            b[nt][0], b[nt][1]);
        }
    }

    // reduce row sums over the 4 q-lanes
#pragma unroll
    for (int of = 1; of <= 2; of <<= 1) {
#pragma unroll
        for (int mt = 0; mt < 2; mt++) {
            lrow[mt][0] += __shfl_xor_sync(0xffffffffu, lrow[mt][0], of);
            lrow[mt][1] += __shfl_xor_sync(0xffffffffu, lrow[mt][1], of);
        }
    }

    // ---- merge jh pairs via (now free) KV stage area ----
    __syncthreads();
    float* Om = (float*)(sm + r * 8192);            // 32 rows x 64 f32
    float* Lm = (float*)(sm + 32768) + r * 32;
    if (jh == 1) {
#pragma unroll
        for (int mt = 0; mt < 2; mt++) {
#pragma unroll
            for (int nt = 0; nt < 8; nt++) {
                const int col = nt * 8 + 2 * q;
                const int row0 = mt * 16 + g, row1 = row0 + 8;
                Om[row0 * 64 + col]     = o[mt][nt][0];
                Om[row0 * 64 + col + 1] = o[mt][nt][1];
                Om[row1 * 64 + col]     = o[mt][nt][2];
                Om[row1 * 64 + col + 1] = o[mt][nt][3];
            }
            if (q == 0) {
                Lm[mt * 16 + g]     = lrow[mt][0];
                Lm[mt * 16 + g + 8] = lrow[mt][1];
            }
        }
    }
    __syncthreads();
    if (jh == 0) {
#pragma unroll
        for (int mt = 0; mt < 2; mt++) {
            const int row0 = mt * 16 + g, row1 = row0 + 8;
            const float inv0 = 1.f / (lrow[mt][0] + Lm[row0]);
            const float inv1 = 1.f / (lrow[mt][1] + Lm[row1]);
            __half* out0 = att + (size_t)(bI * Nn + i0 + m0 + row0) * INTERc + h * HDc;
            __half* out1 = att + (size_t)(bI * Nn + i0 + m0 + row1) * INTERc + h * HDc;
#pragma unroll
            for (int nt = 0; nt < 8; nt++) {
                const int col = nt * 8 + 2 * q;
                *(__half2*)(out0 + col) = __floats2half2_rn(
                    (o[mt][nt][0] + Om[row0 * 64 + col]) * inv0,
                    (o[mt][nt][1] + Om[row0 * 64 + col + 1]) * inv0);
                *(__half2*)(out1 + col) = __floats2half2_rn(
                    (o[mt][nt][2] + Om[row1 * 64 + col]) * inv1,
                    (o[mt][nt][3] + Om[row1 * 64 + col + 1]) * inv1);
            }
        }
    }
}

// ---------------------------------------------------------------------------
extern "C" void kernel_launch(void* const* d_in, const int* in_sizes, int n_in,
                              void* d_out, int out_size) {
    const float* features = (const float*)d_in[0];
    const float* W_qkv    = (const float*)d_in[1];
    const float* W_out    = (const float*)d_in[2];
    float* out = (float*)d_out;

    __half *feat_h, *wqkvT_h, *woutT_h, *qkv_h, *vT_h, *att_h;
    cudaGetSymbolAddress((void**)&feat_h, g_feat_h);
    cudaGetSymbolAddress((void**)&wqkvT_h, g_wqkvT_h);
    cudaGetSymbolAddress((void**)&woutT_h, g_woutT_h);
    cudaGetSymbolAddress((void**)&qkv_h, g_qkv_h);
    cudaGetSymbolAddress((void**)&vT_h, g_vT_h);
    cudaGetSymbolAddress((void**)&att_h, g_att_h);

    static bool attr_set = false;
    if (!attr_set) {
        cudaFuncSetAttribute(gemm_f16,
                             cudaFuncAttributeMaxDynamicSharedMemorySize, 98304);
        cudaFuncSetAttribute(attn_mma,
                             cudaFuncAttributeMaxDynamicSharedMemorySize, 81920);
        attr_set = true;
    }

    // 0) fp16 casts; weights transposed for n-major B tiles
    {
        int n4 = (Bc * Nn * DIMc) / 4;
        h_cast<<<(n4 + 255) / 256, 256>>>((const float4*)features,
                                          (__half2*)feat_h, n4);
        h_cast_T<<<dim3(3 * INTERc / 32, DIMc / 32), 256>>>(W_qkv, wqkvT_h,
                                                            DIMc, 3 * INTERc);
        h_cast_T<<<dim3(DIMc / 32, INTERc / 32), 256>>>(W_out, woutT_h,
                                                        INTERc, DIMc);
    }

    // 1) QKV projection: Q (scaled) + K -> qkv_h; V -> vT_h (fused transpose)
    dim3 g1(3 * INTERc / 128, Bc * Nn / 128);
    gemm_f16<<<g1, 256, 98304>>>(feat_h, wqkvT_h, qkv_h, nullptr, vT_h,
                                 Bc * Nn, 3 * INTERc, DIMc, 1);

    // 2) MMA attention (128-thr CTAs, 32-row warps) -> fp16
    dim3 g2(Nn / 64, Bc * HEADc);
    attn_mma<<<g2, 128, 81920>>>(qkv_h, vT_h, att_h);

    // 3) Output projection -> fp32 final
    dim3 g3(DIMc / 128, Bc * Nn / 128);
    gemm_f16<<<g3, 256, 98304>>>(att_h, woutT_h, nullptr, out, nullptr,
                                 Bc * Nn, DIMc, INTERc, 0);
}

// round 15
// speedup vs baseline: 1.0854x; 1.0199x over previous
#include <cuda_runtime.h>
#include <cuda_fp16.h>
#include <math_constants.h>
#include <cstdint>

#define Bc 4
#define Nn 2048
#define DIMc 1024
#define HEADc 16
#define INTERc 1024
#define HDc 64
#define SCALEc 0.03125f   // INTER^-0.5 = 2^-5 (exact)
#define LOG2E 1.4426950408889634f

// Scratch (device globals). *_h buffers hold fp16.
__device__ __align__(16) __half g_feat_h[(size_t)Bc * Nn * DIMc];
__device__ __align__(16) __half g_wqkvT_h[(size_t)3 * INTERc * DIMc];   // W^T
__device__ __align__(16) __half g_woutT_h[(size_t)DIMc * INTERc];       // W^T
__device__ __align__(16) __half g_qkv_h[(size_t)Bc * Nn * 3 * INTERc];  // Q scaled, K
__device__ __align__(16) __half g_vT_h[(size_t)Bc * HEADc * HDc * Nn];  // [bh][d][tok]
__device__ __align__(16) __half g_att_h[(size_t)Bc * Nn * INTERc];

// ---------------------------------------------------------------------------
// Helpers
// ---------------------------------------------------------------------------
__device__ __forceinline__ uint32_t smem_u32(const void* p) {
    uint32_t a;
    asm("{ .reg .u64 t; cvta.to.shared.u64 t, %1; cvt.u32.u64 %0, t; }"
        : "=r"(a) : "l"(p));
    return a;
}
// pack two f32 -> f16x2 {lo, hi}, exp2 both halves in ONE MUFU
__device__ __forceinline__ uint32_t ex2_h2(float lo, float hi) {
    uint32_t p;
    asm("cvt.rn.f16x2.f32 %0, %1, %2;" : "=r"(p) : "f"(hi), "f"(lo));
    asm("ex2.approx.f16x2 %0, %0;" : "+r"(p));
    return p;
}
__device__ __forceinline__ void cp16(uint32_t dst, const void* src) {
    asm volatile("cp.async.cg.shared.global [%0], [%1], 16;"
                 :: "r"(dst), "l"(src));
}
#define CP_COMMIT() asm volatile("cp.async.commit_group;" ::: "memory")
#define CP_WAIT0()  asm volatile("cp.async.wait_group 0;" ::: "memory")
#define CP_WAIT1()  asm volatile("cp.async.wait_group 1;" ::: "memory")

#define LDMX4(r0, r1, r2, r3, addr) \
    asm volatile("ldmatrix.sync.aligned.m8n8.x4.shared.b16 {%0,%1,%2,%3}, [%4];" \
                 : "=r"(r0), "=r"(r1), "=r"(r2), "=r"(r3) : "r"(addr))

__device__ __forceinline__ void mma_f16(float c[4],
                                        uint32_t a0, uint32_t a1, uint32_t a2, uint32_t a3,
                                        uint32_t b0, uint32_t b1) {
    asm volatile("mma.sync.aligned.m16n8k16.row.col.f32.f16.f16.f32 "
                 "{%0,%1,%2,%3}, {%4,%5,%6,%7}, {%8,%9}, {%0,%1,%2,%3};"
                 : "+f"(c[0]), "+f"(c[1]), "+f"(c[2]), "+f"(c[3])
                 : "r"(a0), "r"(a1), "r"(a2), "r"(a3), "r"(b0), "r"(b1));
}

// ---------------------------------------------------------------------------
// fp16 casts
// ---------------------------------------------------------------------------
__global__ void h_cast(const float4* __restrict__ in, __half2* __restrict__ out,
                       int n4) {
    int i = blockIdx.x * blockDim.x + threadIdx.x;
    if (i < n4) {
        float4 v = in[i];
        out[2 * i]     = __floats2half2_rn(v.x, v.y);
        out[2 * i + 1] = __floats2half2_rn(v.z, v.w);
    }
}

// in: [K][N] f32, out: [N][K] fp16
__global__ void h_cast_T(const float* __restrict__ in, __half* __restrict__ out,
                         int K, int N) {
    __shared__ float t[32][33];
    const int n0 = blockIdx.x << 5, k0 = blockIdx.y << 5;
    const int c = threadIdx.x & 31, r4 = threadIdx.x >> 5;
#pragma unroll
    for (int rr = 0; rr < 32; rr += 8)
        t[r4 + rr][c] = in[(size_t)(k0 + r4 + rr) * N + n0 + c];
    __syncthreads();
#pragma unroll
    for (int rr = 0; rr < 32; rr += 8)
        out[(size_t)(n0 + r4 + rr) * K + k0 + c] = __float2half_rn(t[c][r4 + rr]);
}

// ---------------------------------------------------------------------------
// fp16 mma.sync GEMM, 64x64 warp tiles (128B shared traffic per MMA).
// CTA 128x128, 4 warps (128 thr): warp_m = wid>>1 (64 rows), warp_n = wid&1
// (64 cols). BK=64, 3-stage cp.async (96KB).
// ---------------------------------------------------------------------------
__global__ __launch_bounds__(128, 2)
void gemm_f16(const __half* __restrict__ A, const __half* __restrict__ Bt,
              __half* __restrict__ Ch, float* __restrict__ Cf,
              __half* __restrict__ vT, int M, int Nc, int K, int mode) {
    extern __shared__ char sm[];
    const uint32_t sb = smem_u32(sm);
    const int tid = threadIdx.x;
    const int wid = tid >> 5, lane = tid & 31;
    const int g = lane >> 2, q = lane & 3;
    const int warp_m = wid >> 1;
    const int warp_n = wid & 1;
    const int brow = blockIdx.y << 7;
    const int bcol = blockIdx.x << 7;
    const int NS = K >> 6;

    const int rowA_l = lane & 15;
    const int selA   = lane >> 4;
    const int rowB_l = (lane & 7) + ((lane >> 4) << 3);
    const int selB   = (lane >> 3) & 1;

    auto load_stage = [&](int s) {
        const int k0 = s << 6;
        uint32_t base = sb + (uint32_t)((s % 3) * 32768);
#pragma unroll
        for (int r = 0; r < 8; r++) {
            int ci = tid + 128 * r;
            int m = ci >> 3, kc = ci & 7;
            cp16(base + (uint32_t)(m * 128 + ((kc ^ (m & 7)) << 4)),
                 A + (size_t)(brow + m) * K + k0 + kc * 8);
        }
#pragma unroll
        for (int r = 0; r < 8; r++) {
            int ci = tid + 128 * r;
            int n = ci >> 3, kc = ci & 7;
            cp16(base + 16384u + (uint32_t)(n * 128 + ((kc ^ (n & 7)) << 4)),
                 Bt + (size_t)(bcol + n) * K + k0 + kc * 8);
        }
    };

    float c[4][8][4] = {};

    load_stage(0); CP_COMMIT();
    load_stage(1); CP_COMMIT();

    for (int s = 0; s < NS; s++) {
        CP_WAIT1();
        __syncthreads();

        const uint32_t sA = sb + (uint32_t)((s % 3) * 32768);
        const uint32_t sB = sA + 16384u;

#pragma unroll
        for (int kk = 0; kk < 4; kk++) {
            uint32_t a[4][4];
            const int chA = kk * 2 + selA;
#pragma unroll
            for (int mt = 0; mt < 4; mt++) {
                int row = warp_m * 64 + mt * 16 + rowA_l;
                LDMX4(a[mt][0], a[mt][1], a[mt][2], a[mt][3],
                      sA + (uint32_t)(row * 128 + ((chA ^ (row & 7)) << 4)));
            }
            const int chB = kk * 2 + selB;
#pragma unroll
            for (int ntp = 0; ntp < 4; ntp++) {
                uint32_t b0, b1, b2, b3;
                int row = warp_n * 64 + ntp * 16 + rowB_l;
                LDMX4(b0, b1, b2, b3,
                      sB + (uint32_t)(row * 128 + ((chB ^ (row & 7)) << 4)));
#pragma unroll
                for (int mt = 0; mt < 4; mt++) {
                    mma_f16(c[mt][2 * ntp],     a[mt][0], a[mt][1], a[mt][2], a[mt][3], b0, b1);
                    mma_f16(c[mt][2 * ntp + 1], a[mt][0], a[mt][1], a[mt][2], a[mt][3], b2, b3);
                }
            }
            if (kk == 0) {
                if (s + 2 < NS) load_stage(s + 2);
                CP_COMMIT();
            }
        }
    }

    if (mode && bcol >= 2 * INTERc) {
#pragma unroll
        for (int mt = 0; mt < 4; mt++) {
#pragma unroll
            for (int nt = 0; nt < 8; nt++) {
                int row = brow + warp_m * 64 + mt * 16 + g;
                int col = bcol - 2 * INTERc + warp_n * 64 + nt * 8 + q * 2;
                int bI = row >> 11, tok = row & 2047;
                int h = col >> 6, d = col & 63;
                __half* base = vT + (((size_t)(bI * 16 + h) * 64 + d) * Nn) + tok;
                base[0]      = __float2half_rn(c[mt][nt][0]);
                base[Nn]     = __float2half_rn(c[mt][nt][1]);
                base[8]      = __float2half_rn(c[mt][nt][2]);
                base[Nn + 8] = __float2half_rn(c[mt][nt][3]);
            }
        }
    } else if (mode) {
        const float fs = (bcol < INTERc) ? (SCALEc * LOG2E) : 1.0f;
#pragma unroll
        for (int mt = 0; mt < 4; mt++) {
#pragma unroll
            for (int nt = 0; nt < 8; nt++) {
                int row = brow + warp_m * 64 + mt * 16 + g;
                int col = bcol + warp_n * 64 + nt * 8 + q * 2;
                *(__half2*)(Ch + (size_t)row * Nc + col) =
                    __floats2half2_rn(c[mt][nt][0] * fs, c[mt][nt][1] * fs);
                *(__half2*)(Ch + (size_t)(row + 8) * Nc + col) =
                    __floats2half2_rn(c[mt][nt][2] * fs, c[mt][nt][3] * fs);
            }
        }
    } else {
#pragma unroll
        for (int mt = 0; mt < 4; mt++) {
#pragma unroll
            for (int nt = 0; nt < 8; nt++) {
                int row = brow + warp_m * 64 + mt * 16 + g;
                int col = bcol + warp_n * 64 + nt * 8 + q * 2;
                *(float2*)(Cf + (size_t)row * Nc + col) =
                    make_float2(c[mt][nt][0], c[mt][nt][1]);
                *(float2*)(Cf + (size_t)(row + 8) * Nc + col) =
                    make_float2(c[mt][nt][2], c[mt][nt][3]);
            }
        }
    }
}

// ---------------------------------------------------------------------------
// fp16 MMA flash attention (unchanged winning R13 shape): 32-row warps,
// CTA = 64 Q rows x (b,h), 4 warps. ~160B shared traffic per MMA.
// Smem: 2 x (K 16KB + V 16KB) + 4 x P 4KB = 80KB. 2 CTAs/SM.
// ---------------------------------------------------------------------------
__global__ __launch_bounds__(128, 2)
void attn_mma(const __half* __restrict__ qkv, const __half* __restrict__ vT,
              __half* __restrict__ att) {
    extern __shared__ char sm[];
    const uint32_t sb = smem_u32(sm);
    const int tid = threadIdx.x;
    const int wid = tid >> 5, lane = tid & 31;
    const int g = lane >> 2, q = lane & 3;
    const int r = wid >> 1, jh = wid & 1;
    const int bh = blockIdx.y;
    const int bI = bh >> 4, h = bh & 15;
    const int i0 = blockIdx.x << 6;
    const int m0 = r << 5;

    const int rowK_l = (lane & 7) + ((lane >> 4) << 3);
    const int selK   = (lane >> 3) & 1;
    const int rowP_l = lane & 15;
    const int selP   = lane >> 4;

    const size_t RS = 3 * INTERc;
    const __half* Qb = qkv + (size_t)(bI * Nn) * RS + h * HDc;
    const __half* Kb = Qb + INTERc;
    const __half* Vb = vT + (size_t)bh * HDc * Nn;

    uint32_t aq[2][4][4];
#pragma unroll
    for (int mt = 0; mt < 2; mt++) {
        const __half* q0 = Qb + (size_t)(i0 + m0 + mt * 16 + g) * RS;
        const __half* q1 = q0 + 8 * RS;
#pragma unroll
        for (int kb = 0; kb < 4; kb++) {
            aq[mt][kb][0] = *(const uint32_t*)(q0 + kb * 16 + 2 * q);
            aq[mt][kb][1] = *(const uint32_t*)(q1 + kb * 16 + 2 * q);
            aq[mt][kb][2] = *(const uint32_t*)(q0 + kb * 16 + 2 * q + 8);
            aq[mt][kb][3] = *(const uint32_t*)(q1 + kb * 16 + 2 * q + 8);
        }
    }

    auto load_kv = [&](int s) {
        const int jt = s << 7;
        const uint32_t base = sb + (uint32_t)((s & 1) * 32768);
#pragma unroll
        for (int rr = 0; rr < 8; rr++) {
            int ci = tid + 128 * rr;
            int j = ci >> 3, cch = ci & 7;
            cp16(base + (uint32_t)(j * 128 + ((cch ^ (j & 7)) << 4)),
                 Kb + (size_t)(jt + j) * RS + cch * 8);
        }
#pragma unroll
        for (int rr = 0; rr < 8; rr++) {
            int ci = tid + 128 * rr;
            int d = ci >> 4, cch = ci & 15;
            cp16(base + 16384u + (uint32_t)(d * 256 + ((cch ^ (d & 15)) << 4)),
                 Vb + (size_t)d * Nn + jt + cch * 8);
        }
    };

    float o[2][8][4] = {};
    float lrow[2][2] = {};
    char* Pwc = sm + 65536 + wid * 4096;
    const uint32_t sPw = sb + 65536u + (uint32_t)(wid * 4096);

    load_kv(0); CP_COMMIT();

    const int NS = Nn / 128;
    for (int s = 0; s < NS; s++) {
        CP_WAIT0();
        __syncthreads();

        const uint32_t sK = sb + (uint32_t)((s & 1) * 32768);
        const uint32_t sV = sK + 16384u;

        float sc[2][8][4] = {};
#pragma unroll
        for (int kb = 0; kb < 4; kb++) {
            const int chK = kb * 2 + selK;
#pragma unroll
            for (int ntp = 0; ntp < 4; ntp++) {
                uint32_t b0, b1, b2, b3;
                int j = jh * 64 + ntp * 16 + rowK_l;
                LDMX4(b0, b1, b2, b3,
                      sK + (uint32_t)(j * 128 + ((chK ^ (j & 7)) << 4)));
#pragma unroll
                for (int mt = 0; mt < 2; mt++) {
                    mma_f16(sc[mt][2 * ntp],     aq[mt][kb][0], aq[mt][kb][1],
                            aq[mt][kb][2], aq[mt][kb][3], b0, b1);
                    mma_f16(sc[mt][2 * ntp + 1], aq[mt][kb][0], aq[mt][kb][1],
                            aq[mt][kb][2], aq[mt][kb][3], b2, b3);
                }
            }
        }

        if (s + 1 < NS) { load_kv(s + 1); CP_COMMIT(); }

#pragma unroll
        for (int mt = 0; mt < 2; mt++) {
            const int row0 = mt * 16 + g, row1 = row0 + 8;
            float s0 = 0.f, s1 = 0.f;
#pragma unroll
            for (int nt = 0; nt < 8; nt++) {
                uint32_t p01 = ex2_h2(sc[mt][nt][0], sc[mt][nt][1]);
                uint32_t p23 = ex2_h2(sc[mt][nt][2], sc[mt][nt][3]);
                *(uint32_t*)(Pwc + row0 * 128 + ((nt ^ (row0 & 7)) << 4) + 4 * q) = p01;
                *(uint32_t*)(Pwc + row1 * 128 + ((nt ^ (row1 & 7)) << 4) + 4 * q) = p23;
                float2 f01 = __half22float2(*(__half2*)&p01);
                float2 f23 = __half22float2(*(__half2*)&p23);
                s0 += f01.x + f01.y;
                s1 += f23.x + f23.y;
            }
            lrow[mt][0] += s0;
            lrow[mt][1] += s1;
        }
        __syncwarp();

#pragma unroll
        for (int kp = 0; kp < 4; kp++) {
            uint32_t a[2][4];
            const int chP = kp * 2 + selP;
#pragma unroll
            for (int mt = 0; mt < 2; mt++) {
                int rowP = mt * 16 + rowP_l;
                LDMX4(a[mt][0], a[mt][1], a[mt][2], a[mt][3],
                      sPw + (uint32_t)(rowP * 128 + ((chP ^ (rowP & 7)) << 4)));
            }
            uint32_t b[8][2];
            const int chV = jh * 8 + kp * 2 + selK;
#pragma unroll
            for (int ntp = 0; ntp < 4; ntp++) {
                int d = ntp * 16 + rowK_l;
                LDMX4(b[2 * ntp][0], b[2 * ntp][1], b[2 * ntp + 1][0], b[2 * ntp + 1][1],
                      sV + (uint32_t)(d * 256 + ((chV ^ (d & 15)) << 4)));
            }
#pragma unroll
            for (int mt = 0; mt < 2; mt++)
#pragma unroll
                for (int nt = 0; nt < 8; nt++)
                    mma_f16(o[mt][nt], a[mt][0], a[mt][1], a[mt][2], a[mt][3],
                            b[nt][0], b[nt][1]);
        }
    }

#pragma unroll
    for (int of = 1; of <= 2; of <<= 1) {
#pragma unroll
        for (int mt = 0; mt < 2; mt++) {
            lrow[mt][0] += __shfl_xor_sync(0xffffffffu, lrow[mt][0], of);
            lrow[mt][1] += __shfl_xor_sync(0xffffffffu, lrow[mt][1], of);
        }
    }

    __syncthreads();
    float* Om = (float*)(sm + r * 8192);
    float* Lm = (float*)(sm + 32768) + r * 32;
    if (jh == 1) {
#pragma unroll
        for (int mt = 0; mt < 2; mt++) {
#pragma unroll
            for (int nt = 0; nt < 8; nt++) {
                const int col = nt * 8 + 2 * q;
                const int row0 = mt * 16 + g, row1 = row0 + 8;
                Om[row0 * 64 + col]     = o[mt][nt][0];
                Om[row0 * 64 + col + 1] = o[mt][nt][1];
                Om[row1 * 64 + col]     = o[mt][nt][2];
                Om[row1 * 64 + col + 1] = o[mt][nt][3];
            }
            if (q == 0) {
                Lm[mt * 16 + g]     = lrow[mt][0];
                Lm[mt * 16 + g + 8] = lrow[mt][1];
            }
        }
    }
    __syncthreads();
    if (jh == 0) {
#pragma unroll
        for (int mt = 0; mt < 2; mt++) {
            const int row0 = mt * 16 + g, row1 = row0 + 8;
            const float inv0 = 1.f / (lrow[mt][0] + Lm[row0]);
            const float inv1 = 1.f / (lrow[mt][1] + Lm[row1]);
            __half* out0 = att + (size_t)(bI * Nn + i0 + m0 + row0) * INTERc + h * HDc;
            __half* out1 = att + (size_t)(bI * Nn + i0 + m0 + row1) * INTERc + h * HDc;
#pragma unroll
            for (int nt = 0; nt < 8; nt++) {
                const int col = nt * 8 + 2 * q;
                *(__half2*)(out0 + col) = __floats2half2_rn(
                    (o[mt][nt][0] + Om[row0 * 64 + col]) * inv0,
                    (o[mt][nt][1] + Om[row0 * 64 + col + 1]) * inv0);
                *(__half2*)(out1 + col) = __floats2half2_rn(
                    (o[mt][nt][2] + Om[row1 * 64 + col]) * inv1,
                    (o[mt][nt][3] + Om[row1 * 64 + col + 1]) * inv1);
            }
        }
    }
}

// ---------------------------------------------------------------------------
extern "C" void kernel_launch(void* const* d_in, const int* in_sizes, int n_in,
                              void* d_out, int out_size) {
    const float* features = (const float*)d_in[0];
    const float* W_qkv    = (const float*)d_in[1];
    const float* W_out    = (const float*)d_in[2];
    float* out = (float*)d_out;

    __half *feat_h, *wqkvT_h, *woutT_h, *qkv_h, *vT_h, *att_h;
    cudaGetSymbolAddress((void**)&feat_h, g_feat_h);
    cudaGetSymbolAddress((void**)&wqkvT_h, g_wqkvT_h);
    cudaGetSymbolAddress((void**)&woutT_h, g_woutT_h);
    cudaGetSymbolAddress((void**)&qkv_h, g_qkv_h);
    cudaGetSymbolAddress((void**)&vT_h, g_vT_h);
    cudaGetSymbolAddress((void**)&att_h, g_att_h);

    static bool attr_set = false;
    if (!attr_set) {
        cudaFuncSetAttribute(gemm_f16,
                             cudaFuncAttributeMaxDynamicSharedMemorySize, 98304);
        cudaFuncSetAttribute(attn_mma,
                             cudaFuncAttributeMaxDynamicSharedMemorySize, 81920);
        attr_set = true;
    }

    // 0) fp16 casts; weights transposed for n-major B tiles
    {
        int n4 = (Bc * Nn * DIMc) / 4;
        h_cast<<<(n4 + 255) / 256, 256>>>((const float4*)features,
                                          (__half2*)feat_h, n4);
        h_cast_T<<<dim3(3 * INTERc / 32, DIMc / 32), 256>>>(W_qkv, wqkvT_h,
                                                            DIMc, 3 * INTERc);
        h_cast_T<<<dim3(DIMc / 32, INTERc / 32), 256>>>(W_out, woutT_h,
                                                        INTERc, DIMc);
    }

    // 1) QKV projection: Q (scaled) + K -> qkv_h; V -> vT_h (fused transpose)
    dim3 g1(3 * INTERc / 128, Bc * Nn / 128);
    gemm_f16<<<g1, 128, 98304>>>(feat_h, wqkvT_h, qkv_h, nullptr, vT_h,
                                 Bc * Nn, 3 * INTERc, DIMc, 1);

    // 2) MMA attention (128-thr CTAs, 32-row warps) -> fp16
    dim3 g2(Nn / 64, Bc * HEADc);
    attn_mma<<<g2, 128, 81920>>>(qkv_h, vT_h, att_h);

    // 3) Output projection -> fp32 final
    dim3 g3(DIMc / 128, Bc * Nn / 128);
    gemm_f16<<<g3, 128, 98304>>>(att_h, woutT_h, nullptr, out, nullptr,
                                 Bc * Nn, DIMc, INTERc, 0);
}

// round 16
// speedup vs baseline: 1.1704x; 1.0783x over previous
#include <cuda_runtime.h>
#include <cuda_fp16.h>
#include <math_constants.h>
#include <cstdint>

#define Bc 4
#define Nn 2048
#define DIMc 1024
#define HEADc 16
#define INTERc 1024
#define HDc 64
#define SCALEc 0.03125f   // INTER^-0.5 = 2^-5 (exact)
#define LOG2E 1.4426950408889634f

// Scratch (device globals). *_h buffers hold fp16.
__device__ __align__(16) __half g_feat_h[(size_t)Bc * Nn * DIMc];
__device__ __align__(16) __half g_wqkvT_h[(size_t)3 * INTERc * DIMc];   // W^T
__device__ __align__(16) __half g_woutT_h[(size_t)DIMc * INTERc];       // W^T
__device__ __align__(16) __half g_qkv_h[(size_t)Bc * Nn * 3 * INTERc];  // Q scaled, K
__device__ __align__(16) __half g_vT_h[(size_t)Bc * HEADc * HDc * Nn];  // [bh][d][tok]
__device__ __align__(16) __half g_att_h[(size_t)Bc * Nn * INTERc];

// ---------------------------------------------------------------------------
// Helpers
// ---------------------------------------------------------------------------
__device__ __forceinline__ uint32_t smem_u32(const void* p) {
    uint32_t a;
    asm("{ .reg .u64 t; cvta.to.shared.u64 t, %1; cvt.u32.u64 %0, t; }"
        : "=r"(a) : "l"(p));
    return a;
}
// pack two f32 -> f16x2 {lo, hi}, exp2 both halves in ONE MUFU
__device__ __forceinline__ uint32_t ex2_h2(float lo, float hi) {
    uint32_t p;
    asm("cvt.rn.f16x2.f32 %0, %1, %2;" : "=r"(p) : "f"(hi), "f"(lo));
    asm("ex2.approx.f16x2 %0, %0;" : "+r"(p));
    return p;
}
__device__ __forceinline__ void cp16(uint32_t dst, const void* src) {
    asm volatile("cp.async.cg.shared.global [%0], [%1], 16;"
                 :: "r"(dst), "l"(src));
}
#define CP_COMMIT() asm volatile("cp.async.commit_group;" ::: "memory")
#define CP_WAIT0()  asm volatile("cp.async.wait_group 0;" ::: "memory")
#define CP_WAIT1()  asm volatile("cp.async.wait_group 1;" ::: "memory")

#define LDMX4(r0, r1, r2, r3, addr) \
    asm volatile("ldmatrix.sync.aligned.m8n8.x4.shared.b16 {%0,%1,%2,%3}, [%4];" \
                 : "=r"(r0), "=r"(r1), "=r"(r2), "=r"(r3) : "r"(addr))

__device__ __forceinline__ void mma_f16(float c[4],
                                        uint32_t a0, uint32_t a1, uint32_t a2, uint32_t a3,
                                        uint32_t b0, uint32_t b1) {
    asm volatile("mma.sync.aligned.m16n8k16.row.col.f32.f16.f16.f32 "
                 "{%0,%1,%2,%3}, {%4,%5,%6,%7}, {%8,%9}, {%0,%1,%2,%3};"
                 : "+f"(c[0]), "+f"(c[1]), "+f"(c[2]), "+f"(c[3])
                 : "r"(a0), "r"(a1), "r"(a2), "r"(a3), "r"(b0), "r"(b1));
}

// ---------------------------------------------------------------------------
// fp16 casts
// ---------------------------------------------------------------------------
__global__ void h_cast(const float4* __restrict__ in, __half2* __restrict__ out,
                       int n4) {
    int i = blockIdx.x * blockDim.x + threadIdx.x;
    if (i < n4) {
        float4 v = in[i];
        out[2 * i]     = __floats2half2_rn(v.x, v.y);
        out[2 * i + 1] = __floats2half2_rn(v.z, v.w);
    }
}

// in: [K][N] f32, out: [N][K] fp16
__global__ void h_cast_T(const float* __restrict__ in, __half* __restrict__ out,
                         int K, int N) {
    __shared__ float t[32][33];
    const int n0 = blockIdx.x << 5, k0 = blockIdx.y << 5;
    const int c = threadIdx.x & 31, r4 = threadIdx.x >> 5;
#pragma unroll
    for (int rr = 0; rr < 32; rr += 8)
        t[r4 + rr][c] = in[(size_t)(k0 + r4 + rr) * N + n0 + c];
    __syncthreads();
#pragma unroll
    for (int rr = 0; rr < 32; rr += 8)
        out[(size_t)(n0 + r4 + rr) * K + k0 + c] = __float2half_rn(t[c][r4 + rr]);
}

// ---------------------------------------------------------------------------
// fp16 mma.sync GEMM, 64x64 warp tiles (unchanged from R14).
// ---------------------------------------------------------------------------
__global__ __launch_bounds__(128, 2)
void gemm_f16(const __half* __restrict__ A, const __half* __restrict__ Bt,
              __half* __restrict__ Ch, float* __restrict__ Cf,
              __half* __restrict__ vT, int M, int Nc, int K, int mode) {
    extern __shared__ char sm[];
    const uint32_t sb = smem_u32(sm);
    const int tid = threadIdx.x;
    const int wid = tid >> 5, lane = tid & 31;
    const int g = lane >> 2, q = lane & 3;
    const int warp_m = wid >> 1;
    const int warp_n = wid & 1;
    const int brow = blockIdx.y << 7;
    const int bcol = blockIdx.x << 7;
    const int NS = K >> 6;

    const int rowA_l = lane & 15;
    const int selA   = lane >> 4;
    const int rowB_l = (lane & 7) + ((lane >> 4) << 3);
    const int selB   = (lane >> 3) & 1;

    auto load_stage = [&](int s) {
        const int k0 = s << 6;
        uint32_t base = sb + (uint32_t)((s % 3) * 32768);
#pragma unroll
        for (int r = 0; r < 8; r++) {
            int ci = tid + 128 * r;
            int m = ci >> 3, kc = ci & 7;
            cp16(base + (uint32_t)(m * 128 + ((kc ^ (m & 7)) << 4)),
                 A + (size_t)(brow + m) * K + k0 + kc * 8);
        }
#pragma unroll
        for (int r = 0; r < 8; r++) {
            int ci = tid + 128 * r;
            int n = ci >> 3, kc = ci & 7;
            cp16(base + 16384u + (uint32_t)(n * 128 + ((kc ^ (n & 7)) << 4)),
                 Bt + (size_t)(bcol + n) * K + k0 + kc * 8);
        }
    };

    float c[4][8][4] = {};

    load_stage(0); CP_COMMIT();
    load_stage(1); CP_COMMIT();

    for (int s = 0; s < NS; s++) {
        CP_WAIT1();
        __syncthreads();

        const uint32_t sA = sb + (uint32_t)((s % 3) * 32768);
        const uint32_t sB = sA + 16384u;

#pragma unroll
        for (int kk = 0; kk < 4; kk++) {
            uint32_t a[4][4];
            const int chA = kk * 2 + selA;
#pragma unroll
            for (int mt = 0; mt < 4; mt++) {
                int row = warp_m * 64 + mt * 16 + rowA_l;
                LDMX4(a[mt][0], a[mt][1], a[mt][2], a[mt][3],
                      sA + (uint32_t)(row * 128 + ((chA ^ (row & 7)) << 4)));
            }
            const int chB = kk * 2 + selB;
#pragma unroll
            for (int ntp = 0; ntp < 4; ntp++) {
                uint32_t b0, b1, b2, b3;
                int row = warp_n * 64 + ntp * 16 + rowB_l;
                LDMX4(b0, b1, b2, b3,
                      sB + (uint32_t)(row * 128 + ((chB ^ (row & 7)) << 4)));
#pragma unroll
                for (int mt = 0; mt < 4; mt++) {
                    mma_f16(c[mt][2 * ntp],     a[mt][0], a[mt][1], a[mt][2], a[mt][3], b0, b1);
                    mma_f16(c[mt][2 * ntp + 1], a[mt][0], a[mt][1], a[mt][2], a[mt][3], b2, b3);
                }
            }
            if (kk == 0) {
                if (s + 2 < NS) load_stage(s + 2);
                CP_COMMIT();
            }
        }
    }

    if (mode && bcol >= 2 * INTERc) {
#pragma unroll
        for (int mt = 0; mt < 4; mt++) {
#pragma unroll
            for (int nt = 0; nt < 8; nt++) {
                int row = brow + warp_m * 64 + mt * 16 + g;
                int col = bcol - 2 * INTERc + warp_n * 64 + nt * 8 + q * 2;
                int bI = row >> 11, tok = row & 2047;
                int h = col >> 6, d = col & 63;
                __half* base = vT + (((size_t)(bI * 16 + h) * 64 + d) * Nn) + tok;
                base[0]      = __float2half_rn(c[mt][nt][0]);
                base[Nn]     = __float2half_rn(c[mt][nt][1]);
                base[8]      = __float2half_rn(c[mt][nt][2]);
                base[Nn + 8] = __float2half_rn(c[mt][nt][3]);
            }
        }
    } else if (mode) {
        const float fs = (bcol < INTERc) ? (SCALEc * LOG2E) : 1.0f;
#pragma unroll
        for (int mt = 0; mt < 4; mt++) {
#pragma unroll
            for (int nt = 0; nt < 8; nt++) {
                int row = brow + warp_m * 64 + mt * 16 + g;
                int col = bcol + warp_n * 64 + nt * 8 + q * 2;
                *(__half2*)(Ch + (size_t)row * Nc + col) =
                    __floats2half2_rn(c[mt][nt][0] * fs, c[mt][nt][1] * fs);
                *(__half2*)(Ch + (size_t)(row + 8) * Nc + col) =
                    __floats2half2_rn(c[mt][nt][2] * fs, c[mt][nt][3] * fs);
            }
        }
    } else {
#pragma unroll
        for (int mt = 0; mt < 4; mt++) {
#pragma unroll
            for (int nt = 0; nt < 8; nt++) {
                int row = brow + warp_m * 64 + mt * 16 + g;
                int col = bcol + warp_n * 64 + nt * 8 + q * 2;
                *(float2*)(Cf + (size_t)row * Nc + col) =
                    make_float2(c[mt][nt][0], c[mt][nt][1]);
                *(float2*)(Cf + (size_t)(row + 8) * Nc + col) =
                    make_float2(c[mt][nt][2], c[mt][nt][3]);
            }
        }
    }
}

// ---------------------------------------------------------------------------
// fp16 MMA flash attention, REGISTER-RESIDENT P.
// The m16n8k16 C-fragment layout of S is identical to the A-fragment layout
// needed for P@V (thread owns rows {g,g+8} x cols {2q,2q+1} in both), so P
// goes S-regs -> ex2.f16x2 -> packed A-frags with NO smem round-trip.
// CTA = 64 Q rows x (b,h), 4 warps: warp (r, jh) = rows r*32..+31, 64-key half.
// Smem: 2 x (K 16KB + V 16KB) = 64KB. 2 CTAs/SM.
// ---------------------------------------------------------------------------
__global__ __launch_bounds__(128, 2)
void attn_mma(const __half* __restrict__ qkv, const __half* __restrict__ vT,
              __half* __restrict__ att) {
    extern __shared__ char sm[];
    const uint32_t sb = smem_u32(sm);
    const int tid = threadIdx.x;
    const int wid = tid >> 5, lane = tid & 31;
    const int g = lane >> 2, q = lane & 3;
    const int r = wid >> 1, jh = wid & 1;
    const int bh = blockIdx.y;
    const int bI = bh >> 4, h = bh & 15;
    const int i0 = blockIdx.x << 6;
    const int m0 = r << 5;

    const int rowK_l = (lane & 7) + ((lane >> 4) << 3);
    const int selK   = (lane >> 3) & 1;

    const size_t RS = 3 * INTERc;
    const __half* Qb = qkv + (size_t)(bI * Nn) * RS + h * HDc;
    const __half* Kb = Qb + INTERc;
    const __half* Vb = vT + (size_t)bh * HDc * Nn;

    uint32_t aq[2][4][4];
#pragma unroll
    for (int mt = 0; mt < 2; mt++) {
        const __half* q0 = Qb + (size_t)(i0 + m0 + mt * 16 + g) * RS;
        const __half* q1 = q0 + 8 * RS;
#pragma unroll
        for (int kb = 0; kb < 4; kb++) {
            aq[mt][kb][0] = *(const uint32_t*)(q0 + kb * 16 + 2 * q);
            aq[mt][kb][1] = *(const uint32_t*)(q1 + kb * 16 + 2 * q);
            aq[mt][kb][2] = *(const uint32_t*)(q0 + kb * 16 + 2 * q + 8);
            aq[mt][kb][3] = *(const uint32_t*)(q1 + kb * 16 + 2 * q + 8);
        }
    }

    auto load_kv = [&](int s) {
        const int jt = s << 7;
        const uint32_t base = sb + (uint32_t)((s & 1) * 32768);
#pragma unroll
        for (int rr = 0; rr < 8; rr++) {
            int ci = tid + 128 * rr;
            int j = ci >> 3, cch = ci & 7;
            cp16(base + (uint32_t)(j * 128 + ((cch ^ (j & 7)) << 4)),
                 Kb + (size_t)(jt + j) * RS + cch * 8);
        }
#pragma unroll
        for (int rr = 0; rr < 8; rr++) {
            int ci = tid + 128 * rr;
            int d = ci >> 4, cch = ci & 15;
            cp16(base + 16384u + (uint32_t)(d * 256 + ((cch ^ (d & 15)) << 4)),
                 Vb + (size_t)d * Nn + jt + cch * 8);
        }
    };

    float o[2][8][4] = {};
    float lrow[2][2] = {};

    load_kv(0); CP_COMMIT();

    const int NS = Nn / 128;
    for (int s = 0; s < NS; s++) {
        CP_WAIT0();
        __syncthreads();

        const uint32_t sK = sb + (uint32_t)((s & 1) * 32768);
        const uint32_t sV = sK + 16384u;

        // ---- S = Q @ K^T over this warp's 64-j half ----
        float sc[2][8][4] = {};
#pragma unroll
        for (int kb = 0; kb < 4; kb++) {
            const int chK = kb * 2 + selK;
#pragma unroll
            for (int ntp = 0; ntp < 4; ntp++) {
                uint32_t b0, b1, b2, b3;
                int j = jh * 64 + ntp * 16 + rowK_l;
                LDMX4(b0, b1, b2, b3,
                      sK + (uint32_t)(j * 128 + ((chK ^ (j & 7)) << 4)));
#pragma unroll
                for (int mt = 0; mt < 2; mt++) {
                    mma_f16(sc[mt][2 * ntp],     aq[mt][kb][0], aq[mt][kb][1],
                            aq[mt][kb][2], aq[mt][kb][3], b0, b1);
                    mma_f16(sc[mt][2 * ntp + 1], aq[mt][kb][0], aq[mt][kb][1],
                            aq[mt][kb][2], aq[mt][kb][3], b2, b3);
                }
            }
        }

        if (s + 1 < NS) { load_kv(s + 1); CP_COMMIT(); }

        // ---- P = exp2(S) directly into PV A-fragments (register-only) ----
        // A-frag for k16 block kp: a0=rows g cols 2q..2q+1 of nt=2kp,
        // a1=rows g+8 same, a2/a3 = same from nt=2kp+1.
        uint32_t ap[2][4][4];
#pragma unroll
        for (int mt = 0; mt < 2; mt++) {
            float s0 = 0.f, s1 = 0.f;
#pragma unroll
            for (int kp = 0; kp < 4; kp++) {
                uint32_t p0 = ex2_h2(sc[mt][2 * kp][0],     sc[mt][2 * kp][1]);
                uint32_t p1 = ex2_h2(sc[mt][2 * kp][2],     sc[mt][2 * kp][3]);
                uint32_t p2 = ex2_h2(sc[mt][2 * kp + 1][0], sc[mt][2 * kp + 1][1]);
                uint32_t p3 = ex2_h2(sc[mt][2 * kp + 1][2], sc[mt][2 * kp + 1][3]);
                ap[mt][kp][0] = p0; ap[mt][kp][1] = p1;
                ap[mt][kp][2] = p2; ap[mt][kp][3] = p3;
                float2 f0 = __half22float2(*(__half2*)&p0);
                float2 f1 = __half22float2(*(__half2*)&p1);
                float2 f2 = __half22float2(*(__half2*)&p2);
                float2 f3 = __half22float2(*(__half2*)&p3);
                s0 += f0.x + f0.y + f2.x + f2.y;
                s1 += f1.x + f1.y + f3.x + f3.y;
            }
            lrow[mt][0] += s0;
            lrow[mt][1] += s1;
        }

        // ---- O += P @ V (A-frags in registers; V via ldmatrix) ----
#pragma unroll
        for (int kp = 0; kp < 4; kp++) {
            uint32_t b[8][2];
            const int chV = jh * 8 + kp * 2 + selK;
#pragma unroll
            for (int ntp = 0; ntp < 4; ntp++) {
                int d = ntp * 16 + rowK_l;
                LDMX4(b[2 * ntp][0], b[2 * ntp][1], b[2 * ntp + 1][0], b[2 * ntp + 1][1],
                      sV + (uint32_t)(d * 256 + ((chV ^ (d & 15)) << 4)));
            }
#pragma unroll
            for (int mt = 0; mt < 2; mt++)
#pragma unroll
                for (int nt = 0; nt < 8; nt++)
                    mma_f16(o[mt][nt], ap[mt][kp][0], ap[mt][kp][1],
                            ap[mt][kp][2], ap[mt][kp][3], b[nt][0], b[nt][1]);
        }
    }

    // reduce row sums over the 4 q-lanes (sum over j)
#pragma unroll
    for (int of = 1; of <= 2; of <<= 1) {
#pragma unroll
        for (int mt = 0; mt < 2; mt++) {
            lrow[mt][0] += __shfl_xor_sync(0xffffffffu, lrow[mt][0], of);
            lrow[mt][1] += __shfl_xor_sync(0xffffffffu, lrow[mt][1], of);
        }
    }

    // ---- merge jh pairs via (now free) KV stage area ----
    __syncthreads();
    float* Om = (float*)(sm + r * 8192);
    float* Lm = (float*)(sm + 32768) + r * 32;
    if (jh == 1) {
#pragma unroll
        for (int mt = 0; mt < 2; mt++) {
#pragma unroll
            for (int nt = 0; nt < 8; nt++) {
                const int col = nt * 8 + 2 * q;
                const int row0 = mt * 16 + g, row1 = row0 + 8;
                Om[row0 * 64 + col]     = o[mt][nt][0];
                Om[row0 * 64 + col + 1] = o[mt][nt][1];
                Om[row1 * 64 + col]     = o[mt][nt][2];
                Om[row1 * 64 + col + 1] = o[mt][nt][3];
            }
            if (q == 0) {
                Lm[mt * 16 + g]     = lrow[mt][0];
                Lm[mt * 16 + g + 8] = lrow[mt][1];
            }
        }
    }
    __syncthreads();
    if (jh == 0) {
#pragma unroll
        for (int mt = 0; mt < 2; mt++) {
            const int row0 = mt * 16 + g, row1 = row0 + 8;
            const float inv0 = 1.f / (lrow[mt][0] + Lm[row0]);
            const float inv1 = 1.f / (lrow[mt][1] + Lm[row1]);
            __half* out0 = att + (size_t)(bI * Nn + i0 + m0 + row0) * INTERc + h * HDc;
            __half* out1 = att + (size_t)(bI * Nn + i0 + m0 + row1) * INTERc + h * HDc;
#pragma unroll
            for (int nt = 0; nt < 8; nt++) {
                const int col = nt * 8 + 2 * q;
                *(__half2*)(out0 + col) = __floats2half2_rn(
                    (o[mt][nt][0] + Om[row0 * 64 + col]) * inv0,
                    (o[mt][nt][1] + Om[row0 * 64 + col + 1]) * inv0);
                *(__half2*)(out1 + col) = __floats2half2_rn(
                    (o[mt][nt][2] + Om[row1 * 64 + col]) * inv1,
                    (o[mt][nt][3] + Om[row1 * 64 + col + 1]) * inv1);
            }
        }
    }
}

// ---------------------------------------------------------------------------
extern "C" void kernel_launch(void* const* d_in, const int* in_sizes, int n_in,
                              void* d_out, int out_size) {
    const float* features = (const float*)d_in[0];
    const float* W_qkv    = (const float*)d_in[1];
    const float* W_out    = (const float*)d_in[2];
    float* out = (float*)d_out;

    __half *feat_h, *wqkvT_h, *woutT_h, *qkv_h, *vT_h, *att_h;
    cudaGetSymbolAddress((void**)&feat_h, g_feat_h);
    cudaGetSymbolAddress((void**)&wqkvT_h, g_wqkvT_h);
    cudaGetSymbolAddress((void**)&woutT_h, g_woutT_h);
    cudaGetSymbolAddress((void**)&qkv_h, g_qkv_h);
    cudaGetSymbolAddress((void**)&vT_h, g_vT_h);
    cudaGetSymbolAddress((void**)&att_h, g_att_h);

    static bool attr_set = false;
    if (!attr_set) {
        cudaFuncSetAttribute(gemm_f16,
                             cudaFuncAttributeMaxDynamicSharedMemorySize, 98304);
        cudaFuncSetAttribute(attn_mma,
                             cudaFuncAttributeMaxDynamicSharedMemorySize, 65536);
        attr_set = true;
    }

    // 0) fp16 casts; weights transposed for n-major B tiles
    {
        int n4 = (Bc * Nn * DIMc) / 4;
        h_cast<<<(n4 + 255) / 256, 256>>>((const float4*)features,
                                          (__half2*)feat_h, n4);
        h_cast_T<<<dim3(3 * INTERc / 32, DIMc / 32), 256>>>(W_qkv, wqkvT_h,
                                                            DIMc, 3 * INTERc);
        h_cast_T<<<dim3(DIMc / 32, INTERc / 32), 256>>>(W_out, woutT_h,
                                                        INTERc, DIMc);
    }

    // 1) QKV projection: Q (scaled) + K -> qkv_h; V -> vT_h (fused transpose)
    dim3 g1(3 * INTERc / 128, Bc * Nn / 128);
    gemm_f16<<<g1, 128, 98304>>>(feat_h, wqkvT_h, qkv_h, nullptr, vT_h,
                                 Bc * Nn, 3 * INTERc, DIMc, 1);

    // 2) MMA attention (register-resident P) -> fp16
    dim3 g2(Nn / 64, Bc * HEADc);
    attn_mma<<<g2, 128, 65536>>>(qkv_h, vT_h, att_h);

    // 3) Output projection -> fp32 final
    dim3 g3(DIMc / 128, Bc * Nn / 128);
    gemm_f16<<<g3, 128, 98304>>>(att_h, woutT_h, nullptr, out, nullptr,
                                 Bc * Nn, DIMc, INTERc, 0);
}

// round 17
// speedup vs baseline: 1.1774x; 1.0060x over previous
#include <cuda_runtime.h>
#include <cuda_fp16.h>
#include <math_constants.h>
#include <cstdint>

#define Bc 4
#define Nn 2048
#define DIMc 1024
#define HEADc 16
#define INTERc 1024
#define HDc 64
#define SCALEc 0.03125f   // INTER^-0.5 = 2^-5 (exact)
#define LOG2E 1.4426950408889634f

// Scratch (device globals). *_h buffers hold fp16.
__device__ __align__(16) __half g_feat_h[(size_t)Bc * Nn * DIMc];
__device__ __align__(16) __half g_wqkvT_h[(size_t)3 * INTERc * DIMc];   // W^T
__device__ __align__(16) __half g_woutT_h[(size_t)DIMc * INTERc];       // W^T
__device__ __align__(16) __half g_qkv_h[(size_t)Bc * Nn * 3 * INTERc];  // Q scaled, K
__device__ __align__(16) __half g_vT_h[(size_t)Bc * HEADc * HDc * Nn];  // [bh][d][tok]
__device__ __align__(16) __half g_att_h[(size_t)Bc * Nn * INTERc];

// ---------------------------------------------------------------------------
// Helpers
// ---------------------------------------------------------------------------
__device__ __forceinline__ uint32_t smem_u32(const void* p) {
    uint32_t a;
    asm("{ .reg .u64 t; cvta.to.shared.u64 t, %1; cvt.u32.u64 %0, t; }"
        : "=r"(a) : "l"(p));
    return a;
}
// pack two f32 -> f16x2 {lo, hi}, exp2 both halves in ONE MUFU
__device__ __forceinline__ uint32_t ex2_h2(float lo, float hi) {
    uint32_t p;
    asm("cvt.rn.f16x2.f32 %0, %1, %2;" : "=r"(p) : "f"(hi), "f"(lo));
    asm("ex2.approx.f16x2 %0, %0;" : "+r"(p));
    return p;
}
__device__ __forceinline__ void cp16(uint32_t dst, const void* src) {
    asm volatile("cp.async.cg.shared.global [%0], [%1], 16;"
                 :: "r"(dst), "l"(src));
}
#define CP_COMMIT() asm volatile("cp.async.commit_group;" ::: "memory")
#define CP_WAIT0()  asm volatile("cp.async.wait_group 0;" ::: "memory")
#define CP_WAIT1()  asm volatile("cp.async.wait_group 1;" ::: "memory")

#define LDMX4(r0, r1, r2, r3, addr) \
    asm volatile("ldmatrix.sync.aligned.m8n8.x4.shared.b16 {%0,%1,%2,%3}, [%4];" \
                 : "=r"(r0), "=r"(r1), "=r"(r2), "=r"(r3) : "r"(addr))

__device__ __forceinline__ void mma_f16(float c[4],
                                        uint32_t a0, uint32_t a1, uint32_t a2, uint32_t a3,
                                        uint32_t b0, uint32_t b1) {
    asm volatile("mma.sync.aligned.m16n8k16.row.col.f32.f16.f16.f32 "
                 "{%0,%1,%2,%3}, {%4,%5,%6,%7}, {%8,%9}, {%0,%1,%2,%3};"
                 : "+f"(c[0]), "+f"(c[1]), "+f"(c[2]), "+f"(c[3])
                 : "r"(a0), "r"(a1), "r"(a2), "r"(a3), "r"(b0), "r"(b1));
}

// ---------------------------------------------------------------------------
// fp16 casts
// ---------------------------------------------------------------------------
__global__ void h_cast(const float4* __restrict__ in, __half2* __restrict__ out,
                       int n4) {
    int i = blockIdx.x * blockDim.x + threadIdx.x;
    if (i < n4) {
        float4 v = in[i];
        out[2 * i]     = __floats2half2_rn(v.x, v.y);
        out[2 * i + 1] = __floats2half2_rn(v.z, v.w);
    }
}

// Fused weight transposes: z=0 -> W_qkv [1024][3072] -> [3072][1024],
//                          z=1 -> W_out [1024][1024] -> [1024][1024]^T
__global__ void h_cast_T2(const float* __restrict__ wqkv, __half* __restrict__ wqkvT,
                          const float* __restrict__ wout, __half* __restrict__ woutT) {
    __shared__ float t[32][33];
    const int z = blockIdx.z;
    const int N = z ? DIMc : 3 * INTERc;       // source cols
    const int K = z ? INTERc : DIMc;           // source rows
    if (z && blockIdx.x >= (unsigned)(DIMc / 32)) return;
    const float* in = z ? wout : wqkv;
    __half* out = z ? woutT : wqkvT;
    const int n0 = blockIdx.x << 5, k0 = blockIdx.y << 5;
    const int c = threadIdx.x & 31, r4 = threadIdx.x >> 5;
#pragma unroll
    for (int rr = 0; rr < 32; rr += 8)
        t[r4 + rr][c] = in[(size_t)(k0 + r4 + rr) * N + n0 + c];
    __syncthreads();
#pragma unroll
    for (int rr = 0; rr < 32; rr += 8)
        out[(size_t)(n0 + r4 + rr) * K + k0 + c] = __float2half_rn(t[c][r4 + rr]);
}

// ---------------------------------------------------------------------------
// fp16 mma.sync GEMM, 64x64 warp tiles (unchanged from R14).
// ---------------------------------------------------------------------------
__global__ __launch_bounds__(128, 2)
void gemm_f16(const __half* __restrict__ A, const __half* __restrict__ Bt,
              __half* __restrict__ Ch, float* __restrict__ Cf,
              __half* __restrict__ vT, int M, int Nc, int K, int mode) {
    extern __shared__ char sm[];
    const uint32_t sb = smem_u32(sm);
    const int tid = threadIdx.x;
    const int wid = tid >> 5, lane = tid & 31;
    const int g = lane >> 2, q = lane & 3;
    const int warp_m = wid >> 1;
    const int warp_n = wid & 1;
    const int brow = blockIdx.y << 7;
    const int bcol = blockIdx.x << 7;
    const int NS = K >> 6;

    const int rowA_l = lane & 15;
    const int selA   = lane >> 4;
    const int rowB_l = (lane & 7) + ((lane >> 4) << 3);
    const int selB   = (lane >> 3) & 1;

    auto load_stage = [&](int s) {
        const int k0 = s << 6;
        uint32_t base = sb + (uint32_t)((s % 3) * 32768);
#pragma unroll
        for (int r = 0; r < 8; r++) {
            int ci = tid + 128 * r;
            int m = ci >> 3, kc = ci & 7;
            cp16(base + (uint32_t)(m * 128 + ((kc ^ (m & 7)) << 4)),
                 A + (size_t)(brow + m) * K + k0 + kc * 8);
        }
#pragma unroll
        for (int r = 0; r < 8; r++) {
            int ci = tid + 128 * r;
            int n = ci >> 3, kc = ci & 7;
            cp16(base + 16384u + (uint32_t)(n * 128 + ((kc ^ (n & 7)) << 4)),
                 Bt + (size_t)(bcol + n) * K + k0 + kc * 8);
        }
    };

    float c[4][8][4] = {};

    load_stage(0); CP_COMMIT();
    load_stage(1); CP_COMMIT();

    for (int s = 0; s < NS; s++) {
        CP_WAIT1();
        __syncthreads();

        const uint32_t sA = sb + (uint32_t)((s % 3) * 32768);
        const uint32_t sB = sA + 16384u;

#pragma unroll
        for (int kk = 0; kk < 4; kk++) {
            uint32_t a[4][4];
            const int chA = kk * 2 + selA;
#pragma unroll
            for (int mt = 0; mt < 4; mt++) {
                int row = warp_m * 64 + mt * 16 + rowA_l;
                LDMX4(a[mt][0], a[mt][1], a[mt][2], a[mt][3],
                      sA + (uint32_t)(row * 128 + ((chA ^ (row & 7)) << 4)));
            }
            const int chB = kk * 2 + selB;
#pragma unroll
            for (int ntp = 0; ntp < 4; ntp++) {
                uint32_t b0, b1, b2, b3;
                int row = warp_n * 64 + ntp * 16 + rowB_l;
                LDMX4(b0, b1, b2, b3,
                      sB + (uint32_t)(row * 128 + ((chB ^ (row & 7)) << 4)));
#pragma unroll
                for (int mt = 0; mt < 4; mt++) {
                    mma_f16(c[mt][2 * ntp],     a[mt][0], a[mt][1], a[mt][2], a[mt][3], b0, b1);
                    mma_f16(c[mt][2 * ntp + 1], a[mt][0], a[mt][1], a[mt][2], a[mt][3], b2, b3);
                }
            }
            if (kk == 0) {
                if (s + 2 < NS) load_stage(s + 2);
                CP_COMMIT();
            }
        }
    }

    if (mode && bcol >= 2 * INTERc) {
#pragma unroll
        for (int mt = 0; mt < 4; mt++) {
#pragma unroll
            for (int nt = 0; nt < 8; nt++) {
                int row = brow + warp_m * 64 + mt * 16 + g;
                int col = bcol - 2 * INTERc + warp_n * 64 + nt * 8 + q * 2;
                int bI = row >> 11, tok = row & 2047;
                int h = col >> 6, d = col & 63;
                __half* base = vT + (((size_t)(bI * 16 + h) * 64 + d) * Nn) + tok;
                base[0]      = __float2half_rn(c[mt][nt][0]);
                base[Nn]     = __float2half_rn(c[mt][nt][1]);
                base[8]      = __float2half_rn(c[mt][nt][2]);
                base[Nn + 8] = __float2half_rn(c[mt][nt][3]);
            }
        }
    } else if (mode) {
        const float fs = (bcol < INTERc) ? (SCALEc * LOG2E) : 1.0f;
#pragma unroll
        for (int mt = 0; mt < 4; mt++) {
#pragma unroll
            for (int nt = 0; nt < 8; nt++) {
                int row = brow + warp_m * 64 + mt * 16 + g;
                int col = bcol + warp_n * 64 + nt * 8 + q * 2;
                *(__half2*)(Ch + (size_t)row * Nc + col) =
                    __floats2half2_rn(c[mt][nt][0] * fs, c[mt][nt][1] * fs);
                *(__half2*)(Ch + (size_t)(row + 8) * Nc + col) =
                    __floats2half2_rn(c[mt][nt][2] * fs, c[mt][nt][3] * fs);
            }
        }
    } else {
#pragma unroll
        for (int mt = 0; mt < 4; mt++) {
#pragma unroll
            for (int nt = 0; nt < 8; nt++) {
                int row = brow + warp_m * 64 + mt * 16 + g;
                int col = bcol + warp_n * 64 + nt * 8 + q * 2;
                *(float2*)(Cf + (size_t)row * Nc + col) =
                    make_float2(c[mt][nt][0], c[mt][nt][1]);
                *(float2*)(Cf + (size_t)(row + 8) * Nc + col) =
                    make_float2(c[mt][nt][2], c[mt][nt][3]);
            }
        }
    }
}

// ---------------------------------------------------------------------------
// fp16 MMA flash attention, register-resident P, 3-stage KV pipeline.
// CTA = 64 Q rows x (b,h), 4 warps: warp (r, jh) = rows r*32..+31, 64-key half.
// Smem: 3 x (K 16KB + V 16KB) = 96KB. 2 CTAs/SM.
// ---------------------------------------------------------------------------
__global__ __launch_bounds__(128, 2)
void attn_mma(const __half* __restrict__ qkv, const __half* __restrict__ vT,
              __half* __restrict__ att) {
    extern __shared__ char sm[];
    const uint32_t sb = smem_u32(sm);
    const int tid = threadIdx.x;
    const int wid = tid >> 5, lane = tid & 31;
    const int g = lane >> 2, q = lane & 3;
    const int r = wid >> 1, jh = wid & 1;
    const int bh = blockIdx.y;
    const int bI = bh >> 4, h = bh & 15;
    const int i0 = blockIdx.x << 6;
    const int m0 = r << 5;

    const int rowK_l = (lane & 7) + ((lane >> 4) << 3);
    const int selK   = (lane >> 3) & 1;

    const size_t RS = 3 * INTERc;
    const __half* Qb = qkv + (size_t)(bI * Nn) * RS + h * HDc;
    const __half* Kb = Qb + INTERc;
    const __half* Vb = vT + (size_t)bh * HDc * Nn;

    auto load_kv = [&](int s) {
        const int jt = s << 7;
        const uint32_t base = sb + (uint32_t)((s % 3) * 32768);
#pragma unroll
        for (int rr = 0; rr < 8; rr++) {
            int ci = tid + 128 * rr;
            int j = ci >> 3, cch = ci & 7;
            cp16(base + (uint32_t)(j * 128 + ((cch ^ (j & 7)) << 4)),
                 Kb + (size_t)(jt + j) * RS + cch * 8);
        }
#pragma unroll
        for (int rr = 0; rr < 8; rr++) {
            int ci = tid + 128 * rr;
            int d = ci >> 4, cch = ci & 15;
            cp16(base + 16384u + (uint32_t)(d * 256 + ((cch ^ (d & 15)) << 4)),
                 Vb + (size_t)d * Nn + jt + cch * 8);
        }
    };

    // kick off pipeline before Q-frag gathers (overlap LDG with cp.async)
    load_kv(0); CP_COMMIT();
    load_kv(1); CP_COMMIT();

    uint32_t aq[2][4][4];
#pragma unroll
    for (int mt = 0; mt < 2; mt++) {
        const __half* q0 = Qb + (size_t)(i0 + m0 + mt * 16 + g) * RS;
        const __half* q1 = q0 + 8 * RS;
#pragma unroll
        for (int kb = 0; kb < 4; kb++) {
            aq[mt][kb][0] = *(const uint32_t*)(q0 + kb * 16 + 2 * q);
            aq[mt][kb][1] = *(const uint32_t*)(q1 + kb * 16 + 2 * q);
            aq[mt][kb][2] = *(const uint32_t*)(q0 + kb * 16 + 2 * q + 8);
            aq[mt][kb][3] = *(const uint32_t*)(q1 + kb * 16 + 2 * q + 8);
        }
    }

    float o[2][8][4] = {};
    float lrow[2][2] = {};

    const int NS = Nn / 128;
    for (int s = 0; s < NS; s++) {
        CP_WAIT1();        // stage s resident; latest group may be in flight
        __syncthreads();
        if (s + 2 < NS) { load_kv(s + 2); CP_COMMIT(); }  // buffer (s-1)%3 free

        const uint32_t sK = sb + (uint32_t)((s % 3) * 32768);
        const uint32_t sV = sK + 16384u;

        // ---- S = Q @ K^T over this warp's 64-j half ----
        float sc[2][8][4] = {};
#pragma unroll
        for (int kb = 0; kb < 4; kb++) {
            const int chK = kb * 2 + selK;
#pragma unroll
            for (int ntp = 0; ntp < 4; ntp++) {
                uint32_t b0, b1, b2, b3;
                int j = jh * 64 + ntp * 16 + rowK_l;
                LDMX4(b0, b1, b2, b3,
                      sK + (uint32_t)(j * 128 + ((chK ^ (j & 7)) << 4)));
#pragma unroll
                for (int mt = 0; mt < 2; mt++) {
                    mma_f16(sc[mt][2 * ntp],     aq[mt][kb][0], aq[mt][kb][1],
                            aq[mt][kb][2], aq[mt][kb][3], b0, b1);
                    mma_f16(sc[mt][2 * ntp + 1], aq[mt][kb][0], aq[mt][kb][1],
                            aq[mt][kb][2], aq[mt][kb][3], b2, b3);
                }
            }
        }

        // ---- P = exp2(S) directly into PV A-fragments (register-only) ----
        uint32_t ap[2][4][4];
#pragma unroll
        for (int mt = 0; mt < 2; mt++) {
            float s0 = 0.f, s1 = 0.f;
#pragma unroll
            for (int kp = 0; kp < 4; kp++) {
                uint32_t p0 = ex2_h2(sc[mt][2 * kp][0],     sc[mt][2 * kp][1]);
                uint32_t p1 = ex2_h2(sc[mt][2 * kp][2],     sc[mt][2 * kp][3]);
                uint32_t p2 = ex2_h2(sc[mt][2 * kp + 1][0], sc[mt][2 * kp + 1][1]);
                uint32_t p3 = ex2_h2(sc[mt][2 * kp + 1][2], sc[mt][2 * kp + 1][3]);
                ap[mt][kp][0] = p0; ap[mt][kp][1] = p1;
                ap[mt][kp][2] = p2; ap[mt][kp][3] = p3;
                float2 f0 = __half22float2(*(__half2*)&p0);
                float2 f1 = __half22float2(*(__half2*)&p1);
                float2 f2 = __half22float2(*(__half2*)&p2);
                float2 f3 = __half22float2(*(__half2*)&p3);
                s0 += f0.x + f0.y + f2.x + f2.y;
                s1 += f1.x + f1.y + f3.x + f3.y;
            }
            lrow[mt][0] += s0;
            lrow[mt][1] += s1;
        }

        // ---- O += P @ V (A-frags in registers; V via ldmatrix) ----
#pragma unroll
        for (int kp = 0; kp < 4; kp++) {
            uint32_t b[8][2];
            const int chV = jh * 8 + kp * 2 + selK;
#pragma unroll
            for (int ntp = 0; ntp < 4; ntp++) {
                int d = ntp * 16 + rowK_l;
                LDMX4(b[2 * ntp][0], b[2 * ntp][1], b[2 * ntp + 1][0], b[2 * ntp + 1][1],
                      sV + (uint32_t)(d * 256 + ((chV ^ (d & 15)) << 4)));
            }
#pragma unroll
            for (int mt = 0; mt < 2; mt++)
#pragma unroll
                for (int nt = 0; nt < 8; nt++)
                    mma_f16(o[mt][nt], ap[mt][kp][0], ap[mt][kp][1],
                            ap[mt][kp][2], ap[mt][kp][3], b[nt][0], b[nt][1]);
        }
    }

    // reduce row sums over the 4 q-lanes (sum over j)
#pragma unroll
    for (int of = 1; of <= 2; of <<= 1) {
#pragma unroll
        for (int mt = 0; mt < 2; mt++) {
            lrow[mt][0] += __shfl_xor_sync(0xffffffffu, lrow[mt][0], of);
            lrow[mt][1] += __shfl_xor_sync(0xffffffffu, lrow[mt][1], of);
        }
    }

    // ---- merge jh pairs via (now free) KV stage area ----
    __syncthreads();
    float* Om = (float*)(sm + r * 8192);
    float* Lm = (float*)(sm + 32768) + r * 32;
    if (jh == 1) {
#pragma unroll
        for (int mt = 0; mt < 2; mt++) {
#pragma unroll
            for (int nt = 0; nt < 8; nt++) {
                const int col = nt * 8 + 2 * q;
                const int row0 = mt * 16 + g, row1 = row0 + 8;
                Om[row0 * 64 + col]     = o[mt][nt][0];
                Om[row0 * 64 + col + 1] = o[mt][nt][1];
                Om[row1 * 64 + col]     = o[mt][nt][2];
                Om[row1 * 64 + col + 1] = o[mt][nt][3];
            }
            if (q == 0) {
                Lm[mt * 16 + g]     = lrow[mt][0];
                Lm[mt * 16 + g + 8] = lrow[mt][1];
            }
        }
    }
    __syncthreads();
    if (jh == 0) {
#pragma unroll
        for (int mt = 0; mt < 2; mt++) {
            const int row0 = mt * 16 + g, row1 = row0 + 8;
            const float inv0 = 1.f / (lrow[mt][0] + Lm[row0]);
            const float inv1 = 1.f / (lrow[mt][1] + Lm[row1]);
            __half* out0 = att + (size_t)(bI * Nn + i0 + m0 + row0) * INTERc + h * HDc;
            __half* out1 = att + (size_t)(bI * Nn + i0 + m0 + row1) * INTERc + h * HDc;
#pragma unroll
            for (int nt = 0; nt < 8; nt++) {
                const int col = nt * 8 + 2 * q;
                *(__half2*)(out0 + col) = __floats2half2_rn(
                    (o[mt][nt][0] + Om[row0 * 64 + col]) * inv0,
                    (o[mt][nt][1] + Om[row0 * 64 + col + 1]) * inv0);
                *(__half2*)(out1 + col) = __floats2half2_rn(
                    (o[mt][nt][2] + Om[row1 * 64 + col]) * inv1,
                    (o[mt][nt][3] + Om[row1 * 64 + col + 1]) * inv1);
            }
        }
    }
}

// ---------------------------------------------------------------------------
extern "C" void kernel_launch(void* const* d_in, const int* in_sizes, int n_in,
                              void* d_out, int out_size) {
    const float* features = (const float*)d_in[0];
    const float* W_qkv    = (const float*)d_in[1];
    const float* W_out    = (const float*)d_in[2];
    float* out = (float*)d_out;

    __half *feat_h, *wqkvT_h, *woutT_h, *qkv_h, *vT_h, *att_h;
    cudaGetSymbolAddress((void**)&feat_h, g_feat_h);
    cudaGetSymbolAddress((void**)&wqkvT_h, g_wqkvT_h);
    cudaGetSymbolAddress((void**)&woutT_h, g_woutT_h);
    cudaGetSymbolAddress((void**)&qkv_h, g_qkv_h);
    cudaGetSymbolAddress((void**)&vT_h, g_vT_h);
    cudaGetSymbolAddress((void**)&att_h, g_att_h);

    static bool attr_set = false;
    if (!attr_set) {
        cudaFuncSetAttribute(gemm_f16,
                             cudaFuncAttributeMaxDynamicSharedMemorySize, 98304);
        cudaFuncSetAttribute(attn_mma,
                             cudaFuncAttributeMaxDynamicSharedMemorySize, 98304);
        attr_set = true;
    }

    // 0) fp16 casts: features (elementwise) + both weight transposes (fused)
    {
        int n4 = (Bc * Nn * DIMc) / 4;
        h_cast<<<(n4 + 255) / 256, 256>>>((const float4*)features,
                                          (__half2*)feat_h, n4);
        h_cast_T2<<<dim3(3 * INTERc / 32, DIMc / 32, 2), 256>>>(
            W_qkv, wqkvT_h, W_out, woutT_h);
    }

    // 1) QKV projection: Q (scaled) + K -> qkv_h; V -> vT_h (fused transpose)
    dim3 g1(3 * INTERc / 128, Bc * Nn / 128);
    gemm_f16<<<g1, 128, 98304>>>(feat_h, wqkvT_h, qkv_h, nullptr, vT_h,
                                 Bc * Nn, 3 * INTERc, DIMc, 1);

    // 2) MMA attention (register-resident P, 3-stage pipeline) -> fp16
    dim3 g2(Nn / 64, Bc * HEADc);
    attn_mma<<<g2, 128, 98304>>>(qkv_h, vT_h, att_h);

    // 3) Output projection -> fp32 final
    dim3 g3(DIMc / 128, Bc * Nn / 128);
    gemm_f16<<<g3, 128, 98304>>>(att_h, woutT_h, nullptr, out, nullptr,
                                 Bc * Nn, DIMc, INTERc, 0);
}